// round 1
// baseline (speedup 1.0000x reference)
#include <cuda_runtime.h>
#include <math.h>

// ---------------- problem constants ----------------
#define BATCH   32
#define HIMG    56
#define WIMG    56
#define CH      512
#define NHEAD   16
#define WS      7
#define SSH     3
#define HD      32
#define NWIN    49          // WS*WS tokens per window
#define NW_IMG  64          // (56/7)^2 windows per image
#define BN      (BATCH*NW_IMG)      // 2048 windows total
#define MTOK    (BN*NWIN)           // 100352 tokens
#define HID     2048
#define SCALE   0.17677669529663687f  // 1/sqrt(32)

// ---------------- scratch buffers ----------------
__device__ float g_wins[(size_t)MTOK*CH];        // LN1 + partitioned
__device__ float g_qkv [(size_t)MTOK*3*CH];      // qkv
__device__ float g_o   [(size_t)MTOK*CH];        // attention out
__device__ float g_proj[(size_t)MTOK*CH];        // proj out (window order)
__device__ float g_y   [(size_t)MTOK*CH];        // LN2 out
__device__ float g_hid [(size_t)MTOK*HID];       // fc1 out

// ---------------- LayerNorm (+ optional shift/partition) ----------------
// blockIdx.x = output token row, 128 threads, 4 channels each (float4).
// mode 0: src row == tok (plain LN)
// mode 1: tok is (window,n) order; src is shifted image pixel (LN1 path)
__global__ __launch_bounds__(128)
void ln_kernel(const float* __restrict__ x, const float* __restrict__ gamma,
               const float* __restrict__ beta, float* __restrict__ out, int mode)
{
    int tok = blockIdx.x;
    int src;
    if (mode == 1) {
        int w = tok / NWIN, n = tok - w * NWIN;
        int b = w >> 6, wi = w & 63;
        int wh = wi >> 3, ww = wi & 7;
        int i = n / WS, j = n - i * WS;
        int hp = wh * WS + i, wp = ww * WS + j;
        int hs = hp + SSH; if (hs >= HIMG) hs -= HIMG;
        int ws_ = wp + SSH; if (ws_ >= WIMG) ws_ -= WIMG;
        src = b * (HIMG * WIMG) + hs * WIMG + ws_;
    } else {
        src = tok;
    }
    int tid = threadIdx.x;
    int c = tid * 4;
    float4 v = *(const float4*)(x + (size_t)src * CH + c);
    float s  = v.x + v.y + v.z + v.w;
    float sq = v.x*v.x + v.y*v.y + v.z*v.z + v.w*v.w;
    #pragma unroll
    for (int off = 16; off; off >>= 1) {
        s  += __shfl_xor_sync(0xffffffffu, s, off);
        sq += __shfl_xor_sync(0xffffffffu, sq, off);
    }
    __shared__ float sh[8];
    int warp = tid >> 5, lane = tid & 31;
    if (lane == 0) { sh[warp] = s; sh[warp + 4] = sq; }
    __syncthreads();
    if (tid == 0) {
        float ts = sh[0] + sh[1] + sh[2] + sh[3];
        float tq = sh[4] + sh[5] + sh[6] + sh[7];
        float mean = ts * (1.0f / CH);
        float var = tq * (1.0f / CH) - mean * mean;
        sh[0] = mean;
        sh[1] = rsqrtf(var + 1e-5f);
    }
    __syncthreads();
    float mean = sh[0], inv = sh[1];
    float4 g4 = *(const float4*)(gamma + c);
    float4 b4 = *(const float4*)(beta + c);
    float4 o4;
    o4.x = (v.x - mean) * inv * g4.x + b4.x;
    o4.y = (v.y - mean) * inv * g4.y + b4.y;
    o4.z = (v.z - mean) * inv * g4.z + b4.z;
    o4.w = (v.w - mean) * inv * g4.w + b4.w;
    *(float4*)(out + (size_t)tok * CH + c) = o4;
}

// ---------------- SGEMM 128x128x8, 256 threads, 8x8 per thread ----------------
// C[M,N] = A[M,K] @ B[K,N] + bias[N], row-major everywhere.
// EPI: 0 = store, 1 = exact GELU then store, 2 = C += result (read-modify-write)
template <int EPI>
__global__ __launch_bounds__(256, 2)
void sgemm_kernel(const float* __restrict__ A, const float* __restrict__ B,
                  const float* __restrict__ bias, float* __restrict__ C,
                  int M, int N, int K)
{
    __shared__ float As[8][128];
    __shared__ float Bs[8][128];
    int tid = threadIdx.x;
    int m0 = blockIdx.y * 128;
    int n0 = blockIdx.x * 128;

    int arow = tid >> 1;           // 0..127
    int acol = (tid & 1) * 4;      // 0 or 4
    int brow = tid >> 5;           // 0..7
    int bcol = (tid & 31) * 4;     // 0..124

    int tx = tid & 15, ty = tid >> 4;

    float acc[8][8];
    #pragma unroll
    for (int i = 0; i < 8; ++i)
        #pragma unroll
        for (int j = 0; j < 8; ++j) acc[i][j] = 0.0f;

    const float* Ab = A + (size_t)(m0 + arow) * K + acol;
    const float* Bb = B + (size_t)brow * N + n0 + bcol;

    for (int k0 = 0; k0 < K; k0 += 8) {
        float4 a = *(const float4*)(Ab + k0);
        float4 b4 = *(const float4*)(Bb + (size_t)k0 * N);
        As[acol + 0][arow] = a.x;
        As[acol + 1][arow] = a.y;
        As[acol + 2][arow] = a.z;
        As[acol + 3][arow] = a.w;
        *(float4*)&Bs[brow][bcol] = b4;
        __syncthreads();
        #pragma unroll
        for (int kk = 0; kk < 8; ++kk) {
            float ra[8], rb[8];
            *(float4*)&ra[0] = *(const float4*)&As[kk][ty * 4];
            *(float4*)&ra[4] = *(const float4*)&As[kk][64 + ty * 4];
            *(float4*)&rb[0] = *(const float4*)&Bs[kk][tx * 4];
            *(float4*)&rb[4] = *(const float4*)&Bs[kk][64 + tx * 4];
            #pragma unroll
            for (int i = 0; i < 8; ++i)
                #pragma unroll
                for (int j = 0; j < 8; ++j)
                    acc[i][j] += ra[i] * rb[j];
        }
        __syncthreads();
    }

    #pragma unroll
    for (int i = 0; i < 8; ++i) {
        int row = m0 + ((i < 4) ? (ty * 4 + i) : (64 + ty * 4 + i - 4));
        #pragma unroll
        for (int jg = 0; jg < 2; ++jg) {
            int col = n0 + jg * 64 + tx * 4;
            float4 bv = *(const float4*)(bias + col);
            float4 r;
            r.x = acc[i][jg * 4 + 0] + bv.x;
            r.y = acc[i][jg * 4 + 1] + bv.y;
            r.z = acc[i][jg * 4 + 2] + bv.z;
            r.w = acc[i][jg * 4 + 3] + bv.w;
            float* cp = C + (size_t)row * N + col;
            if (EPI == 1) {
                r.x = 0.5f * r.x * (1.0f + erff(r.x * 0.70710678118654752f));
                r.y = 0.5f * r.y * (1.0f + erff(r.y * 0.70710678118654752f));
                r.z = 0.5f * r.z * (1.0f + erff(r.z * 0.70710678118654752f));
                r.w = 0.5f * r.w * (1.0f + erff(r.w * 0.70710678118654752f));
            } else if (EPI == 2) {
                float4 old = *(const float4*)cp;
                r.x += old.x; r.y += old.y; r.z += old.z; r.w += old.w;
            }
            *(float4*)cp = r;
        }
    }
}

// ---------------- windowed attention ----------------
// one block per (window b, head h); 256 threads
__global__ __launch_bounds__(256)
void attn_kernel(const float* __restrict__ qkv, const float* __restrict__ table,
                 const int* __restrict__ relidx, const float* __restrict__ mask,
                 float* __restrict__ o)
{
    __shared__ float sq[NWIN * 33];
    __shared__ float sk[NWIN * 33];
    __shared__ float sv[NWIN * 33];
    __shared__ float ss[NWIN * 50];

    int bh = blockIdx.x;
    int b = bh >> 4, h = bh & 15;
    int tid = threadIdx.x;

    for (int idx = tid; idx < NWIN * HD; idx += 256) {
        int n = idx >> 5, d = idx & 31;
        size_t base = (size_t)(b * NWIN + n) * (3 * CH) + h * HD + d;
        sq[n * 33 + d] = qkv[base] * SCALE;
        sk[n * 33 + d] = qkv[base + CH];
        sv[n * 33 + d] = qkv[base + 2 * CH];
    }
    __syncthreads();

    int wi = b & 63;
    for (int idx = tid; idx < NWIN * NWIN; idx += 256) {
        int n = idx / NWIN, m = idx - n * NWIN;
        const float* qp = &sq[n * 33];
        const float* kp = &sk[m * 33];
        float acc = 0.0f;
        #pragma unroll
        for (int d = 0; d < HD; ++d) acc += qp[d] * kp[d];
        acc += table[relidx[idx] * NHEAD + h];
        acc += mask[(size_t)wi * (NWIN * NWIN) + idx];
        ss[n * 50 + m] = acc;
    }
    __syncthreads();

    int warp = tid >> 5, lane = tid & 31;
    for (int r = warp; r < NWIN; r += 8) {
        float v1 = ss[r * 50 + lane];
        float v2 = (lane + 32 < NWIN) ? ss[r * 50 + lane + 32] : -1e30f;
        float mx = fmaxf(v1, v2);
        #pragma unroll
        for (int off = 16; off; off >>= 1)
            mx = fmaxf(mx, __shfl_xor_sync(0xffffffffu, mx, off));
        float e1 = expf(v1 - mx);
        float e2 = (lane + 32 < NWIN) ? expf(v2 - mx) : 0.0f;
        float sum = e1 + e2;
        #pragma unroll
        for (int off = 16; off; off >>= 1)
            sum += __shfl_xor_sync(0xffffffffu, sum, off);
        float inv = 1.0f / sum;
        ss[r * 50 + lane] = e1 * inv;
        if (lane + 32 < NWIN) ss[r * 50 + lane + 32] = e2 * inv;
    }
    __syncthreads();

    for (int idx = tid; idx < NWIN * HD; idx += 256) {
        int n = idx >> 5, d = idx & 31;
        const float* pp = &ss[n * 50];
        float acc = 0.0f;
        #pragma unroll
        for (int m = 0; m < NWIN; ++m) acc += pp[m] * sv[m * 33 + d];
        o[(size_t)(b * NWIN + n) * CH + h * HD + d] = acc;
    }
}

// ---------------- window reverse + roll back + residual ----------------
// blockIdx.x = output token (b, hp0, wp0) order; out = x + proj[mapped]
__global__ __launch_bounds__(128)
void add_reverse_kernel(const float* __restrict__ x, const float* __restrict__ proj,
                        float* __restrict__ out)
{
    int tok = blockIdx.x;
    int b = tok / (HIMG * WIMG);
    int rem = tok - b * (HIMG * WIMG);
    int hp0 = rem / WIMG, wp0 = rem - hp0 * WIMG;
    int hp = hp0 - SSH; if (hp < 0) hp += HIMG;
    int wp = wp0 - SSH; if (wp < 0) wp += WIMG;
    int wh = hp / WS, i = hp - wh * WS;
    int ww = wp / WS, j = wp - ww * WS;
    int src = (b * NW_IMG + wh * 8 + ww) * NWIN + i * WS + j;

    int c = threadIdx.x * 4;
    float4 a = *(const float4*)(x + (size_t)tok * CH + c);
    float4 p = *(const float4*)(proj + (size_t)src * CH + c);
    a.x += p.x; a.y += p.y; a.z += p.z; a.w += p.w;
    *(float4*)(out + (size_t)tok * CH + c) = a;
}

// ---------------- launcher ----------------
extern "C" void kernel_launch(void* const* d_in, const int* in_sizes, int n_in,
                              void* d_out, int out_size)
{
    const float* x        = (const float*)d_in[0];
    const float* norm1_g  = (const float*)d_in[1];
    const float* norm1_b  = (const float*)d_in[2];
    const float* qkv_w    = (const float*)d_in[3];
    const float* qkv_b    = (const float*)d_in[4];
    const float* rel_tab  = (const float*)d_in[5];
    const float* proj_w   = (const float*)d_in[6];
    const float* proj_b   = (const float*)d_in[7];
    const float* norm2_g  = (const float*)d_in[8];
    const float* norm2_b  = (const float*)d_in[9];
    const float* fc1_w    = (const float*)d_in[10];
    const float* fc1_b    = (const float*)d_in[11];
    const float* fc2_w    = (const float*)d_in[12];
    const float* fc2_b    = (const float*)d_in[13];
    const int*   rel_idx  = (const int*)d_in[14];
    const float* attn_msk = (const float*)d_in[15];
    float* out = (float*)d_out;

    float *wins, *qkv, *o, *proj, *y, *hid;
    cudaGetSymbolAddress((void**)&wins, g_wins);
    cudaGetSymbolAddress((void**)&qkv,  g_qkv);
    cudaGetSymbolAddress((void**)&o,    g_o);
    cudaGetSymbolAddress((void**)&proj, g_proj);
    cudaGetSymbolAddress((void**)&y,    g_y);
    cudaGetSymbolAddress((void**)&hid,  g_hid);

    // 1) LN1 + shift + window partition
    ln_kernel<<<MTOK, 128>>>(x, norm1_g, norm1_b, wins, 1);

    // 2) QKV GEMM: (100352 x 512) @ (512 x 1536)
    {
        dim3 grid(3 * CH / 128, MTOK / 128);
        sgemm_kernel<0><<<grid, 256>>>(wins, qkv_w, qkv_b, qkv, MTOK, 3 * CH, CH);
    }

    // 3) windowed attention
    attn_kernel<<<BN * NHEAD, 256>>>(qkv, rel_tab, rel_idx, attn_msk, o);

    // 4) proj GEMM: (100352 x 512) @ (512 x 512)
    {
        dim3 grid(CH / 128, MTOK / 128);
        sgemm_kernel<0><<<grid, 256>>>(o, proj_w, proj_b, proj, MTOK, CH, CH);
    }

    // 5) reverse + roll + residual -> d_out holds x1
    add_reverse_kernel<<<MTOK, 128>>>(x, proj, out);

    // 6) LN2 on x1
    ln_kernel<<<MTOK, 128>>>(out, norm2_g, norm2_b, y, 0);

    // 7) FC1 + GELU: (100352 x 512) @ (512 x 2048)
    {
        dim3 grid(HID / 128, MTOK / 128);
        sgemm_kernel<1><<<grid, 256>>>(y, fc1_w, fc1_b, hid, MTOK, HID, CH);
    }

    // 8) FC2 + residual add into d_out: (100352 x 2048) @ (2048 x 512)
    {
        dim3 grid(CH / 128, MTOK / 128);
        sgemm_kernel<2><<<grid, 256>>>(hid, fc2_w, fc2_b, out, MTOK, CH, HID);
    }

    (void)in_sizes; (void)n_in; (void)out_size;
}

// round 3
// speedup vs baseline: 1.7473x; 1.7473x over previous
#include <cuda_runtime.h>
#include <cuda_bf16.h>
#include <math.h>
#include <stdint.h>

// ---------------- problem constants ----------------
#define BATCH   32
#define HIMG    56
#define WIMG    56
#define CH      512
#define NHEAD   16
#define WS      7
#define SSH     3
#define HD      32
#define NWIN    49
#define NW_IMG  64
#define BN      (BATCH*NW_IMG)      // 2048 windows
#define MTOK    (BN*NWIN)           // 100352 tokens
#define HID     2048
#define SCALE   0.17677669529663687f

// ---------------- scratch ----------------
// R1 timeline: qkv fp32 (616MB) -> proj fp32 -> hid hi/lo bf16 (822MB)
// R2 timeline: wins hi/lo -> o hi/lo -> y hi/lo (205MB)
__device__ __align__(128) unsigned char g_R1[(size_t)MTOK * HID * 4];
__device__ __align__(128) unsigned char g_R2[(size_t)MTOK * CH * 4];

__device__ __align__(128) __nv_bfloat16 g_qkvT_h[3 * CH * CH];
__device__ __align__(128) __nv_bfloat16 g_qkvT_l[3 * CH * CH];
__device__ __align__(128) __nv_bfloat16 g_projT_h[CH * CH];
__device__ __align__(128) __nv_bfloat16 g_projT_l[CH * CH];
__device__ __align__(128) __nv_bfloat16 g_fc1T_h[HID * CH];
__device__ __align__(128) __nv_bfloat16 g_fc1T_l[HID * CH];
__device__ __align__(128) __nv_bfloat16 g_fc2T_h[CH * HID];
__device__ __align__(128) __nv_bfloat16 g_fc2T_l[CH * HID];

// ---------------- helpers ----------------
__device__ __forceinline__ uint32_t smem_u32(const void* p) {
    uint32_t a;
    asm("{ .reg .u64 t; cvta.to.shared.u64 t, %1; cvt.u32.u64 %0, t; }" : "=r"(a) : "l"(p));
    return a;
}
#define CP16(dst, src) \
    asm volatile("cp.async.cg.shared.global [%0], [%1], 16;" :: "r"(dst), "l"(src))
#define CPCOMMIT() asm volatile("cp.async.commit_group;" ::: "memory")
#define CPWAIT1()  asm volatile("cp.async.wait_group 1;" ::: "memory")
#define CPWAIT0()  asm volatile("cp.async.wait_group 0;" ::: "memory")

#define LDSM4(r, a) \
    asm volatile("ldmatrix.sync.aligned.m8n8.x4.shared.b16 {%0,%1,%2,%3}, [%4];" \
        : "=r"((r)[0]), "=r"((r)[1]), "=r"((r)[2]), "=r"((r)[3]) : "r"(a))

__device__ __forceinline__ void mma_bf16(float* c, const uint32_t* a, const uint32_t* b) {
    asm volatile("mma.sync.aligned.m16n8k16.row.col.f32.bf16.bf16.f32 "
        "{%0,%1,%2,%3}, {%4,%5,%6,%7}, {%8,%9}, {%0,%1,%2,%3};"
        : "+f"(c[0]), "+f"(c[1]), "+f"(c[2]), "+f"(c[3])
        : "r"(a[0]), "r"(a[1]), "r"(a[2]), "r"(a[3]), "r"(b[0]), "r"(b[1]));
}

__device__ __forceinline__ void bf_split(float x, __nv_bfloat16& h, __nv_bfloat16& l) {
    h = __float2bfloat16(x);
    l = __float2bfloat16(x - __bfloat162float(h));
}

// SW64-style swizzle for 64B rows: c16 ^= (row>>1)&3
__device__ __forceinline__ uint32_t swz64(int row, int c16) {
    return (uint32_t)(row * 64 + ((c16 ^ ((row >> 1) & 3)) << 4));
}

// ---------------- weight transpose + split: W[K,N] -> Wt_hi/lo[N,K] ----------------
__global__ __launch_bounds__(256)
void wsplit_kernel(const float* __restrict__ W, __nv_bfloat16* __restrict__ oh,
                   __nv_bfloat16* __restrict__ ol, int K, int N)
{
    __shared__ float t[32][33];
    int n0 = blockIdx.x * 32, k0 = blockIdx.y * 32;
    int tx = threadIdx.x & 31, ty = threadIdx.x >> 5;
    #pragma unroll
    for (int i = ty; i < 32; i += 8)
        t[i][tx] = W[(size_t)(k0 + i) * N + n0 + tx];
    __syncthreads();
    #pragma unroll
    for (int i = ty; i < 32; i += 8) {
        float v = t[tx][i];
        __nv_bfloat16 h, l; bf_split(v, h, l);
        size_t idx = (size_t)(n0 + i) * K + k0 + tx;
        oh[idx] = h; ol[idx] = l;
    }
}

// ---------------- LayerNorm -> bf16 hi/lo (mode1: shift+partition) ----------------
__global__ __launch_bounds__(128)
void ln_kernel(const float* __restrict__ x, const float* __restrict__ gamma,
               const float* __restrict__ beta, __nv_bfloat16* __restrict__ oh,
               __nv_bfloat16* __restrict__ ol, int mode)
{
    int tok = blockIdx.x;
    int src;
    if (mode == 1) {
        int w = tok / NWIN, n = tok - w * NWIN;
        int b = w >> 6, wi = w & 63;
        int wh = wi >> 3, ww = wi & 7;
        int i = n / WS, j = n - i * WS;
        int hp = wh * WS + i, wp = ww * WS + j;
        int hs = hp + SSH; if (hs >= HIMG) hs -= HIMG;
        int ws_ = wp + SSH; if (ws_ >= WIMG) ws_ -= WIMG;
        src = b * (HIMG * WIMG) + hs * WIMG + ws_;
    } else {
        src = tok;
    }
    int tid = threadIdx.x;
    int c = tid * 4;
    float4 v = *(const float4*)(x + (size_t)src * CH + c);
    float s  = v.x + v.y + v.z + v.w;
    float sq = v.x*v.x + v.y*v.y + v.z*v.z + v.w*v.w;
    #pragma unroll
    for (int off = 16; off; off >>= 1) {
        s  += __shfl_xor_sync(0xffffffffu, s, off);
        sq += __shfl_xor_sync(0xffffffffu, sq, off);
    }
    __shared__ float sh[8];
    int warp = tid >> 5, lane = tid & 31;
    if (lane == 0) { sh[warp] = s; sh[warp + 4] = sq; }
    __syncthreads();
    if (tid == 0) {
        float ts = sh[0] + sh[1] + sh[2] + sh[3];
        float tq = sh[4] + sh[5] + sh[6] + sh[7];
        float mean = ts * (1.0f / CH);
        float var = tq * (1.0f / CH) - mean * mean;
        sh[0] = mean; sh[1] = rsqrtf(var + 1e-5f);
    }
    __syncthreads();
    float mean = sh[0], inv = sh[1];
    float4 g4 = *(const float4*)(gamma + c);
    float4 b4 = *(const float4*)(beta + c);
    float o0 = (v.x - mean) * inv * g4.x + b4.x;
    float o1 = (v.y - mean) * inv * g4.y + b4.y;
    float o2 = (v.z - mean) * inv * g4.z + b4.z;
    float o3 = (v.w - mean) * inv * g4.w + b4.w;
    __nv_bfloat16 hh[4], ll[4];
    bf_split(o0, hh[0], ll[0]); bf_split(o1, hh[1], ll[1]);
    bf_split(o2, hh[2], ll[2]); bf_split(o3, hh[3], ll[3]);
    size_t base = (size_t)tok * CH + c;
    *(uint2*)(oh + base) = *(uint2*)hh;
    *(uint2*)(ol + base) = *(uint2*)ll;
}

// ---------------- split-bf16 GEMM via mma.sync (HMMA) ----------------
// C[M,N] = A[M,K] @ B^T (B stored [N,K]) + bias, via Ah*Bh + Ah*Bl + Al*Bh.
// EPI 0: store fp32.  EPI 1: GELU -> bf16 hi/lo.  EPI 2: C += result.
// Tile 128x128, 8 warps (each 32x64), K-chunk 32, double-buffered cp.async.
#define TGEMM_SMEM (2 * 32768)
template <int EPI>
__global__ void __launch_bounds__(256, 1)
tgemm(const __nv_bfloat16* __restrict__ Ah, const __nv_bfloat16* __restrict__ Al,
      const __nv_bfloat16* __restrict__ Bh, const __nv_bfloat16* __restrict__ Bl,
      const float* __restrict__ bias, float* __restrict__ C,
      __nv_bfloat16* __restrict__ Ch, __nv_bfloat16* __restrict__ Cl,
      int M, int N, int K)
{
    extern __shared__ __align__(128) char smem[];
    uint32_t sb = smem_u32(smem);
    int tid = threadIdx.x, wid = tid >> 5, lane = tid & 31;
    int m0 = blockIdx.y << 7, n0 = blockIdx.x << 7;
    int wm = wid & 3, wn = wid >> 2;

    // ---- loader coords: thread covers one row's 32B (2x16B) per piece ----
    int lrow = tid >> 1;
    int lc0  = (tid & 1) * 2;
    const char* gAh = (const char*)(Ah + (size_t)(m0 + lrow) * K) + lc0 * 16;
    const char* gAl = (const char*)(Al + (size_t)(m0 + lrow) * K) + lc0 * 16;
    const char* gBh = (const char*)(Bh + (size_t)(n0 + lrow) * K) + lc0 * 16;
    const char* gBl = (const char*)(Bl + (size_t)(n0 + lrow) * K) + lc0 * 16;
    uint32_t d0 = swz64(lrow, lc0);
    uint32_t d1 = swz64(lrow, lc0 + 1);

    // ---- ldmatrix coords ----
    int arow = wm * 32 + (lane & 15);
    uint32_t aterm = (uint32_t)(arow * 64);
    int axor = (arow >> 1) & 3;
    int ac16 = lane >> 4;                     // + 2*k16
    int brow = wn * 64 + ((lane >> 4) & 1) * 8 + (lane & 7);
    uint32_t bterm = (uint32_t)(brow * 64);
    int bxor = (brow >> 1) & 3;
    int bc16 = (lane >> 3) & 1;               // + 2*k16

    float acc[2][8][4];
    #pragma unroll
    for (int i = 0; i < 2; ++i)
        #pragma unroll
        for (int j = 0; j < 8; ++j)
            #pragma unroll
            for (int q = 0; q < 4; ++q) acc[i][j][q] = 0.0f;

    const int nch = K >> 5;

    // prologue: prefetch chunk 0
    {
        uint32_t s = sb;
        CP16(s + d0,         gAh); CP16(s + d1,         gAh + 16);
        CP16(s + 8192 + d0,  gAl); CP16(s + 8192 + d1,  gAl + 16);
        CP16(s + 16384 + d0, gBh); CP16(s + 16384 + d1, gBh + 16);
        CP16(s + 24576 + d0, gBl); CP16(s + 24576 + d1, gBl + 16);
        CPCOMMIT();
    }

    for (int c = 0; c < nch; ++c) {
        if (c + 1 < nch) {
            uint32_t s = sb + ((c + 1) & 1) * 32768;
            size_t go = (size_t)(c + 1) * 64;
            CP16(s + d0,         gAh + go); CP16(s + d1,         gAh + go + 16);
            CP16(s + 8192 + d0,  gAl + go); CP16(s + 8192 + d1,  gAl + go + 16);
            CP16(s + 16384 + d0, gBh + go); CP16(s + 16384 + d1, gBh + go + 16);
            CP16(s + 24576 + d0, gBl + go); CP16(s + 24576 + d1, gBl + go + 16);
            CPCOMMIT();
            CPWAIT1();
        } else {
            CPWAIT0();
        }
        __syncthreads();

        uint32_t sB = sb + (c & 1) * 32768;
        #pragma unroll
        for (int k16 = 0; k16 < 2; ++k16) {
            uint32_t ah[2][4], al[2][4], bh[4][4], bl[4][4];
            uint32_t aoff = aterm + ((((2 * k16 + ac16) ^ axor)) << 4);
            LDSM4(ah[0], sB + aoff);
            LDSM4(ah[1], sB + aoff + 1024);
            LDSM4(al[0], sB + 8192 + aoff);
            LDSM4(al[1], sB + 8192 + aoff + 1024);
            uint32_t boff = bterm + ((((2 * k16 + bc16) ^ bxor)) << 4);
            #pragma unroll
            for (int ng = 0; ng < 4; ++ng) {
                LDSM4(bh[ng], sB + 16384 + boff + ng * 1024);
                LDSM4(bl[ng], sB + 24576 + boff + ng * 1024);
            }
            // pass 1: Ah*Bh
            #pragma unroll
            for (int mt = 0; mt < 2; ++mt)
                #pragma unroll
                for (int ng = 0; ng < 4; ++ng) {
                    mma_bf16(acc[mt][2 * ng],     ah[mt], &bh[ng][0]);
                    mma_bf16(acc[mt][2 * ng + 1], ah[mt], &bh[ng][2]);
                }
            // pass 2: Ah*Bl
            #pragma unroll
            for (int mt = 0; mt < 2; ++mt)
                #pragma unroll
                for (int ng = 0; ng < 4; ++ng) {
                    mma_bf16(acc[mt][2 * ng],     ah[mt], &bl[ng][0]);
                    mma_bf16(acc[mt][2 * ng + 1], ah[mt], &bl[ng][2]);
                }
            // pass 3: Al*Bh
            #pragma unroll
            for (int mt = 0; mt < 2; ++mt)
                #pragma unroll
                for (int ng = 0; ng < 4; ++ng) {
                    mma_bf16(acc[mt][2 * ng],     al[mt], &bh[ng][0]);
                    mma_bf16(acc[mt][2 * ng + 1], al[mt], &bh[ng][2]);
                }
        }
        __syncthreads();
    }

    // ---- epilogue ----
    int r0 = m0 + wm * 32 + (lane >> 2);
    int cb = n0 + wn * 64 + (lane & 3) * 2;
    #pragma unroll
    for (int mt = 0; mt < 2; ++mt) {
        #pragma unroll
        for (int n8 = 0; n8 < 8; ++n8) {
            int col = cb + n8 * 8;
            float2 bv = *(const float2*)(bias + col);
            #pragma unroll
            for (int rt = 0; rt < 2; ++rt) {
                int row = r0 + mt * 16 + rt * 8;
                float vx = acc[mt][n8][rt * 2]     + bv.x;
                float vy = acc[mt][n8][rt * 2 + 1] + bv.y;
                if (EPI == 0) {
                    float2 r = {vx, vy};
                    *(float2*)(C + (size_t)row * N + col) = r;
                } else if (EPI == 1) {
                    float gx = 0.5f * vx * (1.0f + erff(vx * 0.70710678118654752f));
                    float gy = 0.5f * vy * (1.0f + erff(vy * 0.70710678118654752f));
                    __nv_bfloat16 hh[2], ll[2];
                    bf_split(gx, hh[0], ll[0]);
                    bf_split(gy, hh[1], ll[1]);
                    *(uint32_t*)(Ch + (size_t)row * N + col) = *(uint32_t*)hh;
                    *(uint32_t*)(Cl + (size_t)row * N + col) = *(uint32_t*)ll;
                } else {
                    float* cp = C + (size_t)row * N + col;
                    float2 old = *(const float2*)cp;
                    float2 r = {vx + old.x, vy + old.y};
                    *(float2*)cp = r;
                }
            }
        }
    }
}

// ---------------- windowed attention (fp32, outputs bf16 hi/lo) ----------------
__global__ __launch_bounds__(256)
void attn_kernel(const float* __restrict__ qkv, const float* __restrict__ table,
                 const int* __restrict__ relidx, const float* __restrict__ mask,
                 __nv_bfloat16* __restrict__ oh, __nv_bfloat16* __restrict__ ol)
{
    __shared__ float sq[NWIN * 33];
    __shared__ float sk[NWIN * 33];
    __shared__ float sv[NWIN * 33];
    __shared__ float ss[NWIN * 50];

    int bh = blockIdx.x;
    int b = bh >> 4, h = bh & 15;
    int tid = threadIdx.x;

    for (int idx = tid; idx < NWIN * HD; idx += 256) {
        int n = idx >> 5, d = idx & 31;
        size_t base = (size_t)(b * NWIN + n) * (3 * CH) + h * HD + d;
        sq[n * 33 + d] = qkv[base] * SCALE;
        sk[n * 33 + d] = qkv[base + CH];
        sv[n * 33 + d] = qkv[base + 2 * CH];
    }
    __syncthreads();

    int wi = b & 63;
    for (int idx = tid; idx < NWIN * NWIN; idx += 256) {
        int n = idx / NWIN, m = idx - n * NWIN;
        const float* qp = &sq[n * 33];
        const float* kp = &sk[m * 33];
        float acc = 0.0f;
        #pragma unroll
        for (int d = 0; d < HD; ++d) acc += qp[d] * kp[d];
        acc += table[relidx[idx] * NHEAD + h];
        acc += mask[(size_t)wi * (NWIN * NWIN) + idx];
        ss[n * 50 + m] = acc;
    }
    __syncthreads();

    int warp = tid >> 5, lane = tid & 31;
    for (int r = warp; r < NWIN; r += 8) {
        float v1 = ss[r * 50 + lane];
        float v2 = (lane + 32 < NWIN) ? ss[r * 50 + lane + 32] : -1e30f;
        float mx = fmaxf(v1, v2);
        #pragma unroll
        for (int off = 16; off; off >>= 1)
            mx = fmaxf(mx, __shfl_xor_sync(0xffffffffu, mx, off));
        float e1 = expf(v1 - mx);
        float e2 = (lane + 32 < NWIN) ? expf(v2 - mx) : 0.0f;
        float sum = e1 + e2;
        #pragma unroll
        for (int off = 16; off; off >>= 1)
            sum += __shfl_xor_sync(0xffffffffu, sum, off);
        float inv = 1.0f / sum;
        ss[r * 50 + lane] = e1 * inv;
        if (lane + 32 < NWIN) ss[r * 50 + lane + 32] = e2 * inv;
    }
    __syncthreads();

    for (int idx = tid; idx < NWIN * HD; idx += 256) {
        int n = idx >> 5, d = idx & 31;
        const float* pp = &ss[n * 50];
        float acc = 0.0f;
        #pragma unroll
        for (int m = 0; m < NWIN; ++m) acc += pp[m] * sv[m * 33 + d];
        __nv_bfloat16 hv, lv; bf_split(acc, hv, lv);
        size_t oidx = (size_t)(b * NWIN + n) * CH + h * HD + d;
        oh[oidx] = hv; ol[oidx] = lv;
    }
}

// ---------------- window reverse + roll back + residual ----------------
__global__ __launch_bounds__(128)
void add_reverse_kernel(const float* __restrict__ x, const float* __restrict__ proj,
                        float* __restrict__ out)
{
    int tok = blockIdx.x;
    int b = tok / (HIMG * WIMG);
    int rem = tok - b * (HIMG * WIMG);
    int hp0 = rem / WIMG, wp0 = rem - hp0 * WIMG;
    int hp = hp0 - SSH; if (hp < 0) hp += HIMG;
    int wp = wp0 - SSH; if (wp < 0) wp += WIMG;
    int wh = hp / WS, i = hp - wh * WS;
    int ww = wp / WS, j = wp - ww * WS;
    int src = (b * NW_IMG + wh * 8 + ww) * NWIN + i * WS + j;

    int c = threadIdx.x * 4;
    float4 a = *(const float4*)(x + (size_t)tok * CH + c);
    float4 p = *(const float4*)(proj + (size_t)src * CH + c);
    a.x += p.x; a.y += p.y; a.z += p.z; a.w += p.w;
    *(float4*)(out + (size_t)tok * CH + c) = a;
}

// ---------------- launcher ----------------
extern "C" void kernel_launch(void* const* d_in, const int* in_sizes, int n_in,
                              void* d_out, int out_size)
{
    const float* x        = (const float*)d_in[0];
    const float* norm1_g  = (const float*)d_in[1];
    const float* norm1_b  = (const float*)d_in[2];
    const float* qkv_w    = (const float*)d_in[3];
    const float* qkv_b    = (const float*)d_in[4];
    const float* rel_tab  = (const float*)d_in[5];
    const float* proj_w   = (const float*)d_in[6];
    const float* proj_b   = (const float*)d_in[7];
    const float* norm2_g  = (const float*)d_in[8];
    const float* norm2_b  = (const float*)d_in[9];
    const float* fc1_w    = (const float*)d_in[10];
    const float* fc1_b    = (const float*)d_in[11];
    const float* fc2_w    = (const float*)d_in[12];
    const float* fc2_b    = (const float*)d_in[13];
    const int*   rel_idx  = (const int*)d_in[14];
    const float* attn_msk = (const float*)d_in[15];
    float* out = (float*)d_out;

    unsigned char *R1, *R2;
    cudaGetSymbolAddress((void**)&R1, g_R1);
    cudaGetSymbolAddress((void**)&R2, g_R2);
    __nv_bfloat16 *qkvT_h, *qkvT_l, *projT_h, *projT_l, *fc1T_h, *fc1T_l, *fc2T_h, *fc2T_l;
    cudaGetSymbolAddress((void**)&qkvT_h, g_qkvT_h);
    cudaGetSymbolAddress((void**)&qkvT_l, g_qkvT_l);
    cudaGetSymbolAddress((void**)&projT_h, g_projT_h);
    cudaGetSymbolAddress((void**)&projT_l, g_projT_l);
    cudaGetSymbolAddress((void**)&fc1T_h, g_fc1T_h);
    cudaGetSymbolAddress((void**)&fc1T_l, g_fc1T_l);
    cudaGetSymbolAddress((void**)&fc2T_h, g_fc2T_h);
    cudaGetSymbolAddress((void**)&fc2T_l, g_fc2T_l);

    float* qkv  = (float*)R1;
    float* proj = (float*)R1;
    __nv_bfloat16* hid_h = (__nv_bfloat16*)R1;
    __nv_bfloat16* hid_l = (__nv_bfloat16*)(R1 + (size_t)MTOK * HID * 2);
    __nv_bfloat16* act_h = (__nv_bfloat16*)R2;
    __nv_bfloat16* act_l = (__nv_bfloat16*)(R2 + (size_t)MTOK * CH * 2);

    cudaFuncSetAttribute(tgemm<0>, cudaFuncAttributeMaxDynamicSharedMemorySize, TGEMM_SMEM);
    cudaFuncSetAttribute(tgemm<1>, cudaFuncAttributeMaxDynamicSharedMemorySize, TGEMM_SMEM);
    cudaFuncSetAttribute(tgemm<2>, cudaFuncAttributeMaxDynamicSharedMemorySize, TGEMM_SMEM);

    // 0) weight transpose + split
    wsplit_kernel<<<dim3(3 * CH / 32, CH / 32), 256>>>(qkv_w,  qkvT_h, qkvT_l, CH, 3 * CH);
    wsplit_kernel<<<dim3(CH / 32,     CH / 32), 256>>>(proj_w, projT_h, projT_l, CH, CH);
    wsplit_kernel<<<dim3(HID / 32,    CH / 32), 256>>>(fc1_w,  fc1T_h, fc1T_l, CH, HID);
    wsplit_kernel<<<dim3(CH / 32,    HID / 32), 256>>>(fc2_w,  fc2T_h, fc2T_l, HID, CH);

    // 1) LN1 + shift + window partition -> wins hi/lo
    ln_kernel<<<MTOK, 128>>>(x, norm1_g, norm1_b, act_h, act_l, 1);

    // 2) QKV GEMM (100352 x 1536 x 512)
    tgemm<0><<<dim3(3 * CH / 128, MTOK / 128), 256, TGEMM_SMEM>>>(
        act_h, act_l, qkvT_h, qkvT_l, qkv_b, qkv, nullptr, nullptr, MTOK, 3 * CH, CH);

    // 3) attention -> o hi/lo
    attn_kernel<<<BN * NHEAD, 256>>>(qkv, rel_tab, rel_idx, attn_msk, act_h, act_l);

    // 4) proj GEMM (100352 x 512 x 512)
    tgemm<0><<<dim3(CH / 128, MTOK / 128), 256, TGEMM_SMEM>>>(
        act_h, act_l, projT_h, projT_l, proj_b, proj, nullptr, nullptr, MTOK, CH, CH);

    // 5) reverse + roll + residual -> d_out
    add_reverse_kernel<<<MTOK, 128>>>(x, proj, out);

    // 6) LN2 -> y hi/lo
    ln_kernel<<<MTOK, 128>>>(out, norm2_g, norm2_b, act_h, act_l, 0);

    // 7) FC1 + GELU (100352 x 2048 x 512) -> hid hi/lo
    tgemm<1><<<dim3(HID / 128, MTOK / 128), 256, TGEMM_SMEM>>>(
        act_h, act_l, fc1T_h, fc1T_l, fc1_b, nullptr, hid_h, hid_l, MTOK, HID, CH);

    // 8) FC2 + residual into d_out (100352 x 512 x 2048)
    tgemm<2><<<dim3(CH / 128, MTOK / 128), 256, TGEMM_SMEM>>>(
        hid_h, hid_l, fc2T_h, fc2T_l, fc2_b, out, nullptr, nullptr, MTOK, CH, HID);

    (void)in_sizes; (void)n_in; (void)out_size;
}

// round 4
// speedup vs baseline: 2.0275x; 1.1604x over previous
#include <cuda_runtime.h>
#include <cuda_bf16.h>
#include <math.h>
#include <stdint.h>

// ---------------- problem constants ----------------
#define BATCH   32
#define HIMG    56
#define WIMG    56
#define CH      512
#define NHEAD   16
#define WS      7
#define SSH     3
#define HD      32
#define NWIN    49
#define NW_IMG  64
#define BN      (BATCH*NW_IMG)      // 2048 windows
#define MTOK    (BN*NWIN)           // 100352 tokens
#define HID     2048
#define SCALE   0.17677669529663687f

// ---------------- scratch ----------------
__device__ __align__(128) unsigned char g_R1[(size_t)MTOK * HID * 4];
__device__ __align__(128) unsigned char g_R2[(size_t)MTOK * CH * 4];

__device__ __align__(128) __nv_bfloat16 g_qkvT_h[3 * CH * CH];
__device__ __align__(128) __nv_bfloat16 g_qkvT_l[3 * CH * CH];
__device__ __align__(128) __nv_bfloat16 g_projT_h[CH * CH];
__device__ __align__(128) __nv_bfloat16 g_projT_l[CH * CH];
__device__ __align__(128) __nv_bfloat16 g_fc1T_h[HID * CH];
__device__ __align__(128) __nv_bfloat16 g_fc1T_l[HID * CH];
__device__ __align__(128) __nv_bfloat16 g_fc2T_h[CH * HID];
__device__ __align__(128) __nv_bfloat16 g_fc2T_l[CH * HID];

// ---------------- helpers ----------------
__device__ __forceinline__ uint32_t smem_u32(const void* p) {
    uint32_t a;
    asm("{ .reg .u64 t; cvta.to.shared.u64 t, %1; cvt.u32.u64 %0, t; }" : "=r"(a) : "l"(p));
    return a;
}
#define CP16(dst, src) \
    asm volatile("cp.async.cg.shared.global [%0], [%1], 16;" :: "r"(dst), "l"(src))
#define CPCOMMIT() asm volatile("cp.async.commit_group;" ::: "memory")
#define CPWAIT1()  asm volatile("cp.async.wait_group 1;" ::: "memory")
#define CPWAIT0()  asm volatile("cp.async.wait_group 0;" ::: "memory")

#define LDSM4(r, a) \
    asm volatile("ldmatrix.sync.aligned.m8n8.x4.shared.b16 {%0,%1,%2,%3}, [%4];" \
        : "=r"((r)[0]), "=r"((r)[1]), "=r"((r)[2]), "=r"((r)[3]) : "r"(a))

__device__ __forceinline__ void mma_bf16(float* c, const uint32_t* a, const uint32_t* b) {
    asm volatile("mma.sync.aligned.m16n8k16.row.col.f32.bf16.bf16.f32 "
        "{%0,%1,%2,%3}, {%4,%5,%6,%7}, {%8,%9}, {%0,%1,%2,%3};"
        : "+f"(c[0]), "+f"(c[1]), "+f"(c[2]), "+f"(c[3])
        : "r"(a[0]), "r"(a[1]), "r"(a[2]), "r"(a[3]), "r"(b[0]), "r"(b[1]));
}

__device__ __forceinline__ void bf_split(float x, __nv_bfloat16& h, __nv_bfloat16& l) {
    h = __float2bfloat16(x);
    l = __float2bfloat16(x - __bfloat162float(h));
}

// ---------------- weight transpose + split: W[K,N] -> Wt_hi/lo[N,K] ----------------
__global__ __launch_bounds__(256)
void wsplit_kernel(const float* __restrict__ W, __nv_bfloat16* __restrict__ oh,
                   __nv_bfloat16* __restrict__ ol, int K, int N)
{
    __shared__ float t[32][33];
    int n0 = blockIdx.x * 32, k0 = blockIdx.y * 32;
    int tx = threadIdx.x & 31, ty = threadIdx.x >> 5;
    #pragma unroll
    for (int i = ty; i < 32; i += 8)
        t[i][tx] = W[(size_t)(k0 + i) * N + n0 + tx];
    __syncthreads();
    #pragma unroll
    for (int i = ty; i < 32; i += 8) {
        float v = t[tx][i];
        __nv_bfloat16 h, l; bf_split(v, h, l);
        size_t idx = (size_t)(n0 + i) * K + k0 + tx;
        oh[idx] = h; ol[idx] = l;
    }
}

// ---------------- LayerNorm -> bf16 hi/lo (mode1: shift+partition) ----------------
__global__ __launch_bounds__(128)
void ln_kernel(const float* __restrict__ x, const float* __restrict__ gamma,
               const float* __restrict__ beta, __nv_bfloat16* __restrict__ oh,
               __nv_bfloat16* __restrict__ ol, int mode)
{
    int tok = blockIdx.x;
    int src;
    if (mode == 1) {
        int w = tok / NWIN, n = tok - w * NWIN;
        int b = w >> 6, wi = w & 63;
        int wh = wi >> 3, ww = wi & 7;
        int i = n / WS, j = n - i * WS;
        int hp = wh * WS + i, wp = ww * WS + j;
        int hs = hp + SSH; if (hs >= HIMG) hs -= HIMG;
        int ws_ = wp + SSH; if (ws_ >= WIMG) ws_ -= WIMG;
        src = b * (HIMG * WIMG) + hs * WIMG + ws_;
    } else {
        src = tok;
    }
    int tid = threadIdx.x;
    int c = tid * 4;
    float4 v = *(const float4*)(x + (size_t)src * CH + c);
    float s  = v.x + v.y + v.z + v.w;
    float sq = v.x*v.x + v.y*v.y + v.z*v.z + v.w*v.w;
    #pragma unroll
    for (int off = 16; off; off >>= 1) {
        s  += __shfl_xor_sync(0xffffffffu, s, off);
        sq += __shfl_xor_sync(0xffffffffu, sq, off);
    }
    __shared__ float sh[8];
    int warp = tid >> 5, lane = tid & 31;
    if (lane == 0) { sh[warp] = s; sh[warp + 4] = sq; }
    __syncthreads();
    if (tid == 0) {
        float ts = sh[0] + sh[1] + sh[2] + sh[3];
        float tq = sh[4] + sh[5] + sh[6] + sh[7];
        float mean = ts * (1.0f / CH);
        float var = tq * (1.0f / CH) - mean * mean;
        sh[0] = mean; sh[1] = rsqrtf(var + 1e-5f);
    }
    __syncthreads();
    float mean = sh[0], inv = sh[1];
    float4 g4 = *(const float4*)(gamma + c);
    float4 b4 = *(const float4*)(beta + c);
    float o0 = (v.x - mean) * inv * g4.x + b4.x;
    float o1 = (v.y - mean) * inv * g4.y + b4.y;
    float o2 = (v.z - mean) * inv * g4.z + b4.z;
    float o3 = (v.w - mean) * inv * g4.w + b4.w;
    __nv_bfloat16 hh[4], ll[4];
    bf_split(o0, hh[0], ll[0]); bf_split(o1, hh[1], ll[1]);
    bf_split(o2, hh[2], ll[2]); bf_split(o3, hh[3], ll[3]);
    size_t base = (size_t)tok * CH + c;
    *(uint2*)(oh + base) = *(uint2*)hh;
    *(uint2*)(ol + base) = *(uint2*)ll;
}

// ---------------- split-bf16 GEMM via mma.sync ----------------
// Tile 256x128, 16 warps; warp tile 32x64. K-chunk 64, SW128 rows (128B),
// double-buffered cp.async. C = A@B^T + bias; 3 passes Ah*Bh + Ah*Bl + Al*Bh.
#define STG_A_L 32768
#define STG_B_H 65536
#define STG_B_L 81920
#define STG_SZ  98304
#define TGEMM_SMEM (2 * STG_SZ)

template <int EPI>
__global__ void __launch_bounds__(512, 1)
tgemm(const __nv_bfloat16* __restrict__ Ah, const __nv_bfloat16* __restrict__ Al,
      const __nv_bfloat16* __restrict__ Bh, const __nv_bfloat16* __restrict__ Bl,
      const float* __restrict__ bias, float* __restrict__ C,
      __nv_bfloat16* __restrict__ Ch, __nv_bfloat16* __restrict__ Cl,
      int M, int N, int K)
{
    extern __shared__ __align__(128) char smem[];
    uint32_t sb = smem_u32(smem);
    int tid = threadIdx.x, wid = tid >> 5, lane = tid & 31;
    int m0 = blockIdx.y << 8, n0 = blockIdx.x << 7;
    int wm = wid & 7, wn = wid >> 3;

    // ---- loader coords ----
    int ar = tid >> 1, ac = (tid & 1) * 4;        // A: 256 rows, 4 chunks/thread/array
    int br = tid >> 2, bc = (tid & 3) * 2;        // B: 128 rows, 2 chunks/thread/array
    const char* gAh = (const char*)(Ah + (size_t)(m0 + ar) * K) + ac * 16;
    const char* gAl = (const char*)(Al + (size_t)(m0 + ar) * K) + ac * 16;
    const char* gBh = (const char*)(Bh + (size_t)(n0 + br) * K) + bc * 16;
    const char* gBl = (const char*)(Bl + (size_t)(n0 + br) * K) + bc * 16;
    uint32_t swA[4], swB[2];
    #pragma unroll
    for (int j = 0; j < 4; ++j)
        swA[j] = (uint32_t)(ar * 128 + (((ac + j) ^ (ar & 7)) << 4));
    #pragma unroll
    for (int j = 0; j < 2; ++j)
        swB[j] = (uint32_t)(br * 128 + (((bc + j) ^ (br & 7)) << 4));

    // ---- ldmatrix coords ----
    int arow = wm * 32 + (lane & 15);
    uint32_t aterm = (uint32_t)(arow * 128);
    int axor = arow & 7;
    int ac16 = lane >> 4;
    int brow = wn * 64 + ((lane >> 4) & 1) * 8 + (lane & 7);
    uint32_t bterm = (uint32_t)(brow * 128);
    int bxor = brow & 7;
    int bc16 = (lane >> 3) & 1;

    float acc[2][8][4];
    #pragma unroll
    for (int i = 0; i < 2; ++i)
        #pragma unroll
        for (int j = 0; j < 8; ++j)
            #pragma unroll
            for (int q = 0; q < 4; ++q) acc[i][j][q] = 0.0f;

    const int nch = K >> 6;

    // prologue: chunk 0 -> stage 0
    {
        uint32_t s = sb;
        #pragma unroll
        for (int j = 0; j < 4; ++j) {
            CP16(s + swA[j],           gAh + j * 16);
            CP16(s + STG_A_L + swA[j], gAl + j * 16);
        }
        #pragma unroll
        for (int j = 0; j < 2; ++j) {
            CP16(s + STG_B_H + swB[j], gBh + j * 16);
            CP16(s + STG_B_L + swB[j], gBl + j * 16);
        }
        CPCOMMIT();
    }

    for (int c = 0; c < nch; ++c) {
        if (c + 1 < nch) {
            uint32_t s = sb + ((c + 1) & 1) * STG_SZ;
            size_t go = (size_t)(c + 1) * 128;
            #pragma unroll
            for (int j = 0; j < 4; ++j) {
                CP16(s + swA[j],           gAh + go + j * 16);
                CP16(s + STG_A_L + swA[j], gAl + go + j * 16);
            }
            #pragma unroll
            for (int j = 0; j < 2; ++j) {
                CP16(s + STG_B_H + swB[j], gBh + go + j * 16);
                CP16(s + STG_B_L + swB[j], gBl + go + j * 16);
            }
            CPCOMMIT();
            CPWAIT1();
        } else {
            CPWAIT0();
        }
        __syncthreads();

        uint32_t sS = sb + (c & 1) * STG_SZ;
        #pragma unroll
        for (int k16 = 0; k16 < 4; ++k16) {
            uint32_t ah[2][4], al[2][4], bh[4][4], bl[4][4];
            uint32_t aoff = aterm + ((uint32_t)((2 * k16 + ac16) ^ axor) << 4);
            LDSM4(ah[0], sS + aoff);
            LDSM4(ah[1], sS + aoff + 2048);
            LDSM4(al[0], sS + STG_A_L + aoff);
            LDSM4(al[1], sS + STG_A_L + aoff + 2048);
            uint32_t boff = bterm + ((uint32_t)((2 * k16 + bc16) ^ bxor) << 4);
            #pragma unroll
            for (int ng = 0; ng < 4; ++ng) {
                LDSM4(bh[ng], sS + STG_B_H + boff + ng * 2048);
                LDSM4(bl[ng], sS + STG_B_L + boff + ng * 2048);
            }
            #pragma unroll
            for (int mt = 0; mt < 2; ++mt)
                #pragma unroll
                for (int ng = 0; ng < 4; ++ng) {
                    mma_bf16(acc[mt][2 * ng],     ah[mt], &bh[ng][0]);
                    mma_bf16(acc[mt][2 * ng + 1], ah[mt], &bh[ng][2]);
                }
            #pragma unroll
            for (int mt = 0; mt < 2; ++mt)
                #pragma unroll
                for (int ng = 0; ng < 4; ++ng) {
                    mma_bf16(acc[mt][2 * ng],     ah[mt], &bl[ng][0]);
                    mma_bf16(acc[mt][2 * ng + 1], ah[mt], &bl[ng][2]);
                }
            #pragma unroll
            for (int mt = 0; mt < 2; ++mt)
                #pragma unroll
                for (int ng = 0; ng < 4; ++ng) {
                    mma_bf16(acc[mt][2 * ng],     al[mt], &bh[ng][0]);
                    mma_bf16(acc[mt][2 * ng + 1], al[mt], &bh[ng][2]);
                }
        }
        __syncthreads();
    }

    // ---- epilogue ----
    int r0 = m0 + wm * 32 + (lane >> 2);
    int cb = n0 + wn * 64 + (lane & 3) * 2;
    #pragma unroll
    for (int mt = 0; mt < 2; ++mt) {
        #pragma unroll
        for (int n8 = 0; n8 < 8; ++n8) {
            int col = cb + n8 * 8;
            float2 bv = *(const float2*)(bias + col);
            #pragma unroll
            for (int rt = 0; rt < 2; ++rt) {
                int row = r0 + mt * 16 + rt * 8;
                float vx = acc[mt][n8][rt * 2]     + bv.x;
                float vy = acc[mt][n8][rt * 2 + 1] + bv.y;
                if (EPI == 0) {
                    float2 r = {vx, vy};
                    *(float2*)(C + (size_t)row * N + col) = r;
                } else if (EPI == 1) {
                    float gx = 0.5f * vx * (1.0f + erff(vx * 0.70710678118654752f));
                    float gy = 0.5f * vy * (1.0f + erff(vy * 0.70710678118654752f));
                    __nv_bfloat16 hh[2], ll[2];
                    bf_split(gx, hh[0], ll[0]);
                    bf_split(gy, hh[1], ll[1]);
                    *(uint32_t*)(Ch + (size_t)row * N + col) = *(uint32_t*)hh;
                    *(uint32_t*)(Cl + (size_t)row * N + col) = *(uint32_t*)ll;
                } else {
                    float* cp = C + (size_t)row * N + col;
                    float2 old = *(const float2*)cp;
                    float2 r = {vx + old.x, vy + old.y};
                    *(float2*)cp = r;
                }
            }
        }
    }
}

// ---------------- windowed attention (fp32 in, bf16 hi/lo out) ----------------
__global__ __launch_bounds__(256)
void attn_kernel(const float* __restrict__ qkv, const float* __restrict__ table,
                 const int* __restrict__ relidx, const float* __restrict__ mask,
                 __nv_bfloat16* __restrict__ oh, __nv_bfloat16* __restrict__ ol)
{
    __shared__ float sq[NWIN * 33];
    __shared__ float sk[NWIN * 33];
    __shared__ float sv[NWIN * 33];
    __shared__ float ss[NWIN * 50];

    int bh = blockIdx.x;
    int b = bh >> 4, h = bh & 15;
    int tid = threadIdx.x;

    for (int idx = tid; idx < NWIN * HD; idx += 256) {
        int n = idx >> 5, d = idx & 31;
        size_t base = (size_t)(b * NWIN + n) * (3 * CH) + h * HD + d;
        sq[n * 33 + d] = qkv[base] * SCALE;
        sk[n * 33 + d] = qkv[base + CH];
        sv[n * 33 + d] = qkv[base + 2 * CH];
    }
    __syncthreads();

    int wi = b & 63;
    for (int idx = tid; idx < NWIN * NWIN; idx += 256) {
        int n = idx / NWIN, m = idx - n * NWIN;
        const float* qp = &sq[n * 33];
        const float* kp = &sk[m * 33];
        float acc = 0.0f;
        #pragma unroll
        for (int d = 0; d < HD; ++d) acc += qp[d] * kp[d];
        acc += table[relidx[idx] * NHEAD + h];
        acc += mask[(size_t)wi * (NWIN * NWIN) + idx];
        ss[n * 50 + m] = acc;
    }
    __syncthreads();

    int warp = tid >> 5, lane = tid & 31;
    for (int r = warp; r < NWIN; r += 8) {
        float v1 = ss[r * 50 + lane];
        float v2 = (lane + 32 < NWIN) ? ss[r * 50 + lane + 32] : -1e30f;
        float mx = fmaxf(v1, v2);
        #pragma unroll
        for (int off = 16; off; off >>= 1)
            mx = fmaxf(mx, __shfl_xor_sync(0xffffffffu, mx, off));
        float e1 = expf(v1 - mx);
        float e2 = (lane + 32 < NWIN) ? expf(v2 - mx) : 0.0f;
        float sum = e1 + e2;
        #pragma unroll
        for (int off = 16; off; off >>= 1)
            sum += __shfl_xor_sync(0xffffffffu, sum, off);
        float inv = 1.0f / sum;
        ss[r * 50 + lane] = e1 * inv;
        if (lane + 32 < NWIN) ss[r * 50 + lane + 32] = e2 * inv;
    }
    __syncthreads();

    for (int idx = tid; idx < NWIN * HD; idx += 256) {
        int n = idx >> 5, d = idx & 31;
        const float* pp = &ss[n * 50];
        float acc = 0.0f;
        #pragma unroll
        for (int m = 0; m < NWIN; ++m) acc += pp[m] * sv[m * 33 + d];
        __nv_bfloat16 hv, lv; bf_split(acc, hv, lv);
        size_t oidx = (size_t)(b * NWIN + n) * CH + h * HD + d;
        oh[oidx] = hv; ol[oidx] = lv;
    }
}

// ---------------- fused: reverse+roll+residual -> out, then LN2 -> yh/yl ----------------
__global__ __launch_bounds__(128)
void fuse2_kernel(const float* __restrict__ x, const float* __restrict__ proj,
                  const float* __restrict__ gamma, const float* __restrict__ beta,
                  float* __restrict__ out, __nv_bfloat16* __restrict__ yh,
                  __nv_bfloat16* __restrict__ yl)
{
    int tok = blockIdx.x;
    int b = tok / (HIMG * WIMG);
    int rem = tok - b * (HIMG * WIMG);
    int hp0 = rem / WIMG, wp0 = rem - hp0 * WIMG;
    int hp = hp0 - SSH; if (hp < 0) hp += HIMG;
    int wp = wp0 - SSH; if (wp < 0) wp += WIMG;
    int wh = hp / WS, i = hp - wh * WS;
    int ww = wp / WS, j = wp - ww * WS;
    int src = (b * NW_IMG + wh * 8 + ww) * NWIN + i * WS + j;

    int tid = threadIdx.x;
    int c = tid * 4;
    float4 a = *(const float4*)(x + (size_t)tok * CH + c);
    float4 p = *(const float4*)(proj + (size_t)src * CH + c);
    a.x += p.x; a.y += p.y; a.z += p.z; a.w += p.w;
    *(float4*)(out + (size_t)tok * CH + c) = a;

    float s  = a.x + a.y + a.z + a.w;
    float sq = a.x*a.x + a.y*a.y + a.z*a.z + a.w*a.w;
    #pragma unroll
    for (int off = 16; off; off >>= 1) {
        s  += __shfl_xor_sync(0xffffffffu, s, off);
        sq += __shfl_xor_sync(0xffffffffu, sq, off);
    }
    __shared__ float sh[8];
    int warp = tid >> 5, lane = tid & 31;
    if (lane == 0) { sh[warp] = s; sh[warp + 4] = sq; }
    __syncthreads();
    if (tid == 0) {
        float ts = sh[0] + sh[1] + sh[2] + sh[3];
        float tq = sh[4] + sh[5] + sh[6] + sh[7];
        float mean = ts * (1.0f / CH);
        float var = tq * (1.0f / CH) - mean * mean;
        sh[0] = mean; sh[1] = rsqrtf(var + 1e-5f);
    }
    __syncthreads();
    float mean = sh[0], inv = sh[1];
    float4 g4 = *(const float4*)(gamma + c);
    float4 b4 = *(const float4*)(beta + c);
    float o0 = (a.x - mean) * inv * g4.x + b4.x;
    float o1 = (a.y - mean) * inv * g4.y + b4.y;
    float o2 = (a.z - mean) * inv * g4.z + b4.z;
    float o3 = (a.w - mean) * inv * g4.w + b4.w;
    __nv_bfloat16 hh[4], ll[4];
    bf_split(o0, hh[0], ll[0]); bf_split(o1, hh[1], ll[1]);
    bf_split(o2, hh[2], ll[2]); bf_split(o3, hh[3], ll[3]);
    size_t base = (size_t)tok * CH + c;
    *(uint2*)(yh + base) = *(uint2*)hh;
    *(uint2*)(yl + base) = *(uint2*)ll;
}

// ---------------- launcher ----------------
extern "C" void kernel_launch(void* const* d_in, const int* in_sizes, int n_in,
                              void* d_out, int out_size)
{
    const float* x        = (const float*)d_in[0];
    const float* norm1_g  = (const float*)d_in[1];
    const float* norm1_b  = (const float*)d_in[2];
    const float* qkv_w    = (const float*)d_in[3];
    const float* qkv_b    = (const float*)d_in[4];
    const float* rel_tab  = (const float*)d_in[5];
    const float* proj_w   = (const float*)d_in[6];
    const float* proj_b   = (const float*)d_in[7];
    const float* norm2_g  = (const float*)d_in[8];
    const float* norm2_b  = (const float*)d_in[9];
    const float* fc1_w    = (const float*)d_in[10];
    const float* fc1_b    = (const float*)d_in[11];
    const float* fc2_w    = (const float*)d_in[12];
    const float* fc2_b    = (const float*)d_in[13];
    const int*   rel_idx  = (const int*)d_in[14];
    const float* attn_msk = (const float*)d_in[15];
    float* out = (float*)d_out;

    unsigned char *R1, *R2;
    cudaGetSymbolAddress((void**)&R1, g_R1);
    cudaGetSymbolAddress((void**)&R2, g_R2);
    __nv_bfloat16 *qkvT_h, *qkvT_l, *projT_h, *projT_l, *fc1T_h, *fc1T_l, *fc2T_h, *fc2T_l;
    cudaGetSymbolAddress((void**)&qkvT_h, g_qkvT_h);
    cudaGetSymbolAddress((void**)&qkvT_l, g_qkvT_l);
    cudaGetSymbolAddress((void**)&projT_h, g_projT_h);
    cudaGetSymbolAddress((void**)&projT_l, g_projT_l);
    cudaGetSymbolAddress((void**)&fc1T_h, g_fc1T_h);
    cudaGetSymbolAddress((void**)&fc1T_l, g_fc1T_l);
    cudaGetSymbolAddress((void**)&fc2T_h, g_fc2T_h);
    cudaGetSymbolAddress((void**)&fc2T_l, g_fc2T_l);

    float* qkv  = (float*)R1;
    float* proj = (float*)R1;
    __nv_bfloat16* hid_h = (__nv_bfloat16*)R1;
    __nv_bfloat16* hid_l = (__nv_bfloat16*)(R1 + (size_t)MTOK * HID * 2);
    __nv_bfloat16* act_h = (__nv_bfloat16*)R2;
    __nv_bfloat16* act_l = (__nv_bfloat16*)(R2 + (size_t)MTOK * CH * 2);

    cudaFuncSetAttribute(tgemm<0>, cudaFuncAttributeMaxDynamicSharedMemorySize, TGEMM_SMEM);
    cudaFuncSetAttribute(tgemm<1>, cudaFuncAttributeMaxDynamicSharedMemorySize, TGEMM_SMEM);
    cudaFuncSetAttribute(tgemm<2>, cudaFuncAttributeMaxDynamicSharedMemorySize, TGEMM_SMEM);

    // 0) weight transpose + split
    wsplit_kernel<<<dim3(3 * CH / 32, CH / 32), 256>>>(qkv_w,  qkvT_h, qkvT_l, CH, 3 * CH);
    wsplit_kernel<<<dim3(CH / 32,     CH / 32), 256>>>(proj_w, projT_h, projT_l, CH, CH);
    wsplit_kernel<<<dim3(HID / 32,    CH / 32), 256>>>(fc1_w,  fc1T_h, fc1T_l, CH, HID);
    wsplit_kernel<<<dim3(CH / 32,    HID / 32), 256>>>(fc2_w,  fc2T_h, fc2T_l, HID, CH);

    // 1) LN1 + shift + window partition
    ln_kernel<<<MTOK, 128>>>(x, norm1_g, norm1_b, act_h, act_l, 1);

    // 2) QKV GEMM (100352 x 1536 x 512)
    tgemm<0><<<dim3(3 * CH / 128, MTOK / 256), 512, TGEMM_SMEM>>>(
        act_h, act_l, qkvT_h, qkvT_l, qkv_b, qkv, nullptr, nullptr, MTOK, 3 * CH, CH);

    // 3) attention
    attn_kernel<<<BN * NHEAD, 256>>>(qkv, rel_tab, rel_idx, attn_msk, act_h, act_l);

    // 4) proj GEMM (100352 x 512 x 512)
    tgemm<0><<<dim3(CH / 128, MTOK / 256), 512, TGEMM_SMEM>>>(
        act_h, act_l, projT_h, projT_l, proj_b, proj, nullptr, nullptr, MTOK, CH, CH);

    // 5+6) reverse + residual -> d_out, fused LN2 -> y hi/lo
    fuse2_kernel<<<MTOK, 128>>>(x, proj, norm2_g, norm2_b, out, act_h, act_l);

    // 7) FC1 + GELU (100352 x 2048 x 512)
    tgemm<1><<<dim3(HID / 128, MTOK / 256), 512, TGEMM_SMEM>>>(
        act_h, act_l, fc1T_h, fc1T_l, fc1_b, nullptr, hid_h, hid_l, MTOK, HID, CH);

    // 8) FC2 + residual into d_out (100352 x 512 x 2048)
    tgemm<2><<<dim3(CH / 128, MTOK / 256), 512, TGEMM_SMEM>>>(
        hid_h, hid_l, fc2T_h, fc2T_l, fc2_b, out, nullptr, nullptr, MTOK, CH, HID);

    (void)in_sizes; (void)n_in; (void)out_size;
}

// round 5
// speedup vs baseline: 2.4905x; 1.2283x over previous
#include <cuda_runtime.h>
#include <cuda_fp16.h>
#include <math.h>
#include <stdint.h>

// ---------------- problem constants ----------------
#define BATCH   32
#define HIMG    56
#define WIMG    56
#define CH      512
#define NHEAD   16
#define WS      7
#define SSH     3
#define HD      32
#define NWIN    49
#define NW_IMG  64
#define BN      (BATCH*NW_IMG)      // 2048 windows
#define MTOK    (BN*NWIN)           // 100352 tokens
#define HID     2048
#define SCALE   0.17677669529663687f

// ---------------- scratch ----------------
__device__ __align__(128) unsigned char g_R1[(size_t)MTOK * HID * 4];
__device__ __align__(128) unsigned char g_R2[(size_t)MTOK * CH * 4];

__device__ __align__(128) __half g_qkvT[3 * CH * CH];
__device__ __align__(128) __half g_projT[CH * CH];
__device__ __align__(128) __half g_fc1T[HID * CH];
__device__ __align__(128) __half g_fc2T[CH * HID];

// ---------------- helpers ----------------
__device__ __forceinline__ uint32_t smem_u32(const void* p) {
    uint32_t a;
    asm("{ .reg .u64 t; cvta.to.shared.u64 t, %1; cvt.u32.u64 %0, t; }" : "=r"(a) : "l"(p));
    return a;
}
#define CP16(dst, src) \
    asm volatile("cp.async.cg.shared.global [%0], [%1], 16;" :: "r"(dst), "l"(src))
#define CPCOMMIT() asm volatile("cp.async.commit_group;" ::: "memory")
#define CPWAIT1()  asm volatile("cp.async.wait_group 1;" ::: "memory")
#define CPWAIT0()  asm volatile("cp.async.wait_group 0;" ::: "memory")

#define LDSM4(r, a) \
    asm volatile("ldmatrix.sync.aligned.m8n8.x4.shared.b16 {%0,%1,%2,%3}, [%4];" \
        : "=r"((r)[0]), "=r"((r)[1]), "=r"((r)[2]), "=r"((r)[3]) : "r"(a))

__device__ __forceinline__ void mma_f16(float* c, const uint32_t* a, const uint32_t* b) {
    asm volatile("mma.sync.aligned.m16n8k16.row.col.f32.f16.f16.f32 "
        "{%0,%1,%2,%3}, {%4,%5,%6,%7}, {%8,%9}, {%0,%1,%2,%3};"
        : "+f"(c[0]), "+f"(c[1]), "+f"(c[2]), "+f"(c[3])
        : "r"(a[0]), "r"(a[1]), "r"(a[2]), "r"(a[3]), "r"(b[0]), "r"(b[1]));
}

__device__ __forceinline__ void h_split(float x, __half& h, __half& l) {
    h = __float2half_rn(x);
    l = __float2half_rn(x - __half2float(h));
}

// ---------------- weight transpose: W[K,N] -> Wt[N,K] fp16 ----------------
__global__ __launch_bounds__(256)
void wsplit_kernel(const float* __restrict__ W, __half* __restrict__ oh, int K, int N)
{
    __shared__ float t[32][33];
    int n0 = blockIdx.x * 32, k0 = blockIdx.y * 32;
    int tx = threadIdx.x & 31, ty = threadIdx.x >> 5;
    #pragma unroll
    for (int i = ty; i < 32; i += 8)
        t[i][tx] = W[(size_t)(k0 + i) * N + n0 + tx];
    __syncthreads();
    #pragma unroll
    for (int i = ty; i < 32; i += 8)
        oh[(size_t)(n0 + i) * K + k0 + tx] = __float2half_rn(t[tx][i]);
}

// ---------------- LayerNorm -> fp16 hi/lo (mode1: shift+partition) ----------------
__global__ __launch_bounds__(128)
void ln_kernel(const float* __restrict__ x, const float* __restrict__ gamma,
               const float* __restrict__ beta, __half* __restrict__ oh,
               __half* __restrict__ ol, int mode)
{
    int tok = blockIdx.x;
    int src;
    if (mode == 1) {
        int w = tok / NWIN, n = tok - w * NWIN;
        int b = w >> 6, wi = w & 63;
        int wh = wi >> 3, ww = wi & 7;
        int i = n / WS, j = n - i * WS;
        int hp = wh * WS + i, wp = ww * WS + j;
        int hs = hp + SSH; if (hs >= HIMG) hs -= HIMG;
        int ws_ = wp + SSH; if (ws_ >= WIMG) ws_ -= WIMG;
        src = b * (HIMG * WIMG) + hs * WIMG + ws_;
    } else {
        src = tok;
    }
    int tid = threadIdx.x;
    int c = tid * 4;
    float4 v = *(const float4*)(x + (size_t)src * CH + c);
    float s  = v.x + v.y + v.z + v.w;
    float sq = v.x*v.x + v.y*v.y + v.z*v.z + v.w*v.w;
    #pragma unroll
    for (int off = 16; off; off >>= 1) {
        s  += __shfl_xor_sync(0xffffffffu, s, off);
        sq += __shfl_xor_sync(0xffffffffu, sq, off);
    }
    __shared__ float sh[8];
    int warp = tid >> 5, lane = tid & 31;
    if (lane == 0) { sh[warp] = s; sh[warp + 4] = sq; }
    __syncthreads();
    if (tid == 0) {
        float ts = sh[0] + sh[1] + sh[2] + sh[3];
        float tq = sh[4] + sh[5] + sh[6] + sh[7];
        float mean = ts * (1.0f / CH);
        float var = tq * (1.0f / CH) - mean * mean;
        sh[0] = mean; sh[1] = rsqrtf(var + 1e-5f);
    }
    __syncthreads();
    float mean = sh[0], inv = sh[1];
    float4 g4 = *(const float4*)(gamma + c);
    float4 b4 = *(const float4*)(beta + c);
    float o0 = (v.x - mean) * inv * g4.x + b4.x;
    float o1 = (v.y - mean) * inv * g4.y + b4.y;
    float o2 = (v.z - mean) * inv * g4.z + b4.z;
    float o3 = (v.w - mean) * inv * g4.w + b4.w;
    __half hh[4], ll[4];
    h_split(o0, hh[0], ll[0]); h_split(o1, hh[1], ll[1]);
    h_split(o2, hh[2], ll[2]); h_split(o3, hh[3], ll[3]);
    size_t base = (size_t)tok * CH + c;
    *(uint2*)(oh + base) = *(uint2*)hh;
    *(uint2*)(ol + base) = *(uint2*)ll;
}

// ---------------- split-fp16 GEMM via mma.sync ----------------
// C[M,N] = (Ah+Al)[M,K] @ Bh^T (B stored [N,K]) + bias.
// Tile 256x128, 16 warps, warp tile 32x64. K-chunk 64 (128B rows), 2 stages.
#define STG_AL  32768
#define STG_BH  65536
#define STG_SZ  81920
#define TGEMM_SMEM (2 * STG_SZ)

template <int EPI>
__global__ void __launch_bounds__(512, 1)
tgemm(const __half* __restrict__ Ah, const __half* __restrict__ Al,
      const __half* __restrict__ Bh,
      const float* __restrict__ bias, float* __restrict__ C,
      __half* __restrict__ Ch, __half* __restrict__ Cl,
      int M, int N, int K)
{
    extern __shared__ __align__(128) char smem[];
    uint32_t sb = smem_u32(smem);
    int tid = threadIdx.x, wid = tid >> 5, lane = tid & 31;
    int m0 = blockIdx.y << 8, n0 = blockIdx.x << 7;
    int wm = wid & 7, wn = wid >> 3;

    // ---- loader coords ----
    int ar = tid >> 1, ac = (tid & 1) * 4;        // A: 256 rows, 4x16B per thread
    int br = tid >> 2, bc = (tid & 3) * 2;        // B: 128 rows, 2x16B per thread
    const char* gAh = (const char*)(Ah + (size_t)(m0 + ar) * K) + ac * 16;
    const char* gAl = (const char*)(Al + (size_t)(m0 + ar) * K) + ac * 16;
    const char* gBh = (const char*)(Bh + (size_t)(n0 + br) * K) + bc * 16;
    uint32_t swA[4], swB[2];
    #pragma unroll
    for (int j = 0; j < 4; ++j)
        swA[j] = (uint32_t)(ar * 128 + (((ac + j) ^ (ar & 7)) << 4));
    #pragma unroll
    for (int j = 0; j < 2; ++j)
        swB[j] = (uint32_t)(br * 128 + (((bc + j) ^ (br & 7)) << 4));

    // ---- ldmatrix coords ----
    int arow = wm * 32 + (lane & 15);
    uint32_t aterm = (uint32_t)(arow * 128);
    int axor = arow & 7;
    int ac16 = lane >> 4;
    int brow = wn * 64 + ((lane >> 4) & 1) * 8 + (lane & 7);
    uint32_t bterm = (uint32_t)(brow * 128);
    int bxor = brow & 7;
    int bc16 = (lane >> 3) & 1;

    float acc[2][8][4];
    #pragma unroll
    for (int i = 0; i < 2; ++i)
        #pragma unroll
        for (int j = 0; j < 8; ++j)
            #pragma unroll
            for (int q = 0; q < 4; ++q) acc[i][j][q] = 0.0f;

    const int nch = K >> 6;

    // prologue: chunk 0 -> stage 0
    {
        uint32_t s = sb;
        #pragma unroll
        for (int j = 0; j < 4; ++j) {
            CP16(s + swA[j],          gAh + j * 16);
            CP16(s + STG_AL + swA[j], gAl + j * 16);
        }
        #pragma unroll
        for (int j = 0; j < 2; ++j)
            CP16(s + STG_BH + swB[j], gBh + j * 16);
        CPCOMMIT();
    }

    for (int c = 0; c < nch; ++c) {
        if (c + 1 < nch) {
            uint32_t s = sb + ((c + 1) & 1) * STG_SZ;
            size_t go = (size_t)(c + 1) * 128;
            #pragma unroll
            for (int j = 0; j < 4; ++j) {
                CP16(s + swA[j],          gAh + go + j * 16);
                CP16(s + STG_AL + swA[j], gAl + go + j * 16);
            }
            #pragma unroll
            for (int j = 0; j < 2; ++j)
                CP16(s + STG_BH + swB[j], gBh + go + j * 16);
            CPCOMMIT();
            CPWAIT1();
        } else {
            CPWAIT0();
        }
        __syncthreads();

        uint32_t sS = sb + (c & 1) * STG_SZ;
        #pragma unroll
        for (int k16 = 0; k16 < 4; ++k16) {
            uint32_t ah[2][4], al[2][4];
            uint32_t aoff = aterm + ((uint32_t)((2 * k16 + ac16) ^ axor) << 4);
            LDSM4(ah[0], sS + aoff);
            LDSM4(ah[1], sS + aoff + 2048);
            LDSM4(al[0], sS + STG_AL + aoff);
            LDSM4(al[1], sS + STG_AL + aoff + 2048);
            uint32_t boff = bterm + ((uint32_t)((2 * k16 + bc16) ^ bxor) << 4);
            #pragma unroll
            for (int ng = 0; ng < 4; ++ng) {
                uint32_t bh[4];
                LDSM4(bh, sS + STG_BH + boff + ng * 2048);
                #pragma unroll
                for (int mt = 0; mt < 2; ++mt) {
                    mma_f16(acc[mt][2 * ng],     ah[mt], &bh[0]);
                    mma_f16(acc[mt][2 * ng + 1], ah[mt], &bh[2]);
                    mma_f16(acc[mt][2 * ng],     al[mt], &bh[0]);
                    mma_f16(acc[mt][2 * ng + 1], al[mt], &bh[2]);
                }
            }
        }
        __syncthreads();
    }

    // ---- epilogue ----
    int r0 = m0 + wm * 32 + (lane >> 2);
    int cb = n0 + wn * 64 + (lane & 3) * 2;
    #pragma unroll
    for (int mt = 0; mt < 2; ++mt) {
        #pragma unroll
        for (int n8 = 0; n8 < 8; ++n8) {
            int col = cb + n8 * 8;
            float2 bv = *(const float2*)(bias + col);
            #pragma unroll
            for (int rt = 0; rt < 2; ++rt) {
                int row = r0 + mt * 16 + rt * 8;
                float vx = acc[mt][n8][rt * 2]     + bv.x;
                float vy = acc[mt][n8][rt * 2 + 1] + bv.y;
                if (EPI == 0) {
                    float2 r = {vx, vy};
                    *(float2*)(C + (size_t)row * N + col) = r;
                } else if (EPI == 1) {
                    float gx = 0.5f * vx * (1.0f + erff(vx * 0.70710678118654752f));
                    float gy = 0.5f * vy * (1.0f + erff(vy * 0.70710678118654752f));
                    __half hh[2], ll[2];
                    h_split(gx, hh[0], ll[0]);
                    h_split(gy, hh[1], ll[1]);
                    *(uint32_t*)(Ch + (size_t)row * N + col) = *(uint32_t*)hh;
                    *(uint32_t*)(Cl + (size_t)row * N + col) = *(uint32_t*)ll;
                } else {
                    float* cp = C + (size_t)row * N + col;
                    float2 old = *(const float2*)cp;
                    float2 r = {vx + old.x, vy + old.y};
                    *(float2*)cp = r;
                }
            }
        }
    }
}

// ---------------- windowed attention (fp32 in, fp16 hi/lo out) ----------------
__global__ __launch_bounds__(256)
void attn_kernel(const float* __restrict__ qkv, const float* __restrict__ table,
                 const int* __restrict__ relidx, const float* __restrict__ mask,
                 __half* __restrict__ oh, __half* __restrict__ ol)
{
    __shared__ float sq[NWIN * 33];
    __shared__ float sk[NWIN * 33];
    __shared__ float sv[NWIN * 33];
    __shared__ float ss[NWIN * 50];

    int bh = blockIdx.x;
    int b = bh >> 4, h = bh & 15;
    int tid = threadIdx.x;

    for (int idx = tid; idx < NWIN * HD; idx += 256) {
        int n = idx >> 5, d = idx & 31;
        size_t base = (size_t)(b * NWIN + n) * (3 * CH) + h * HD + d;
        sq[n * 33 + d] = qkv[base] * SCALE;
        sk[n * 33 + d] = qkv[base + CH];
        sv[n * 33 + d] = qkv[base + 2 * CH];
    }
    __syncthreads();

    int wi = b & 63;
    for (int idx = tid; idx < NWIN * NWIN; idx += 256) {
        int n = idx / NWIN, m = idx - n * NWIN;
        const float* qp = &sq[n * 33];
        const float* kp = &sk[m * 33];
        float acc = 0.0f;
        #pragma unroll
        for (int d = 0; d < HD; ++d) acc += qp[d] * kp[d];
        acc += table[relidx[idx] * NHEAD + h];
        acc += mask[(size_t)wi * (NWIN * NWIN) + idx];
        ss[n * 50 + m] = acc;
    }
    __syncthreads();

    int warp = tid >> 5, lane = tid & 31;
    for (int r = warp; r < NWIN; r += 8) {
        float v1 = ss[r * 50 + lane];
        float v2 = (lane + 32 < NWIN) ? ss[r * 50 + lane + 32] : -1e30f;
        float mx = fmaxf(v1, v2);
        #pragma unroll
        for (int off = 16; off; off >>= 1)
            mx = fmaxf(mx, __shfl_xor_sync(0xffffffffu, mx, off));
        float e1 = expf(v1 - mx);
        float e2 = (lane + 32 < NWIN) ? expf(v2 - mx) : 0.0f;
        float sum = e1 + e2;
        #pragma unroll
        for (int off = 16; off; off >>= 1)
            sum += __shfl_xor_sync(0xffffffffu, sum, off);
        float inv = 1.0f / sum;
        ss[r * 50 + lane] = e1 * inv;
        if (lane + 32 < NWIN) ss[r * 50 + lane + 32] = e2 * inv;
    }
    __syncthreads();

    for (int idx = tid; idx < NWIN * HD; idx += 256) {
        int n = idx >> 5, d = idx & 31;
        const float* pp = &ss[n * 50];
        float acc = 0.0f;
        #pragma unroll
        for (int m = 0; m < NWIN; ++m) acc += pp[m] * sv[m * 33 + d];
        __half hv, lv; h_split(acc, hv, lv);
        size_t oidx = (size_t)(b * NWIN + n) * CH + h * HD + d;
        oh[oidx] = hv; ol[oidx] = lv;
    }
}

// ---------------- fused: reverse+roll+residual -> out, then LN2 -> yh/yl ----------------
__global__ __launch_bounds__(128)
void fuse2_kernel(const float* __restrict__ x, const float* __restrict__ proj,
                  const float* __restrict__ gamma, const float* __restrict__ beta,
                  float* __restrict__ out, __half* __restrict__ yh,
                  __half* __restrict__ yl)
{
    int tok = blockIdx.x;
    int b = tok / (HIMG * WIMG);
    int rem = tok - b * (HIMG * WIMG);
    int hp0 = rem / WIMG, wp0 = rem - hp0 * WIMG;
    int hp = hp0 - SSH; if (hp < 0) hp += HIMG;
    int wp = wp0 - SSH; if (wp < 0) wp += WIMG;
    int wh = hp / WS, i = hp - wh * WS;
    int ww = wp / WS, j = wp - ww * WS;
    int src = (b * NW_IMG + wh * 8 + ww) * NWIN + i * WS + j;

    int tid = threadIdx.x;
    int c = tid * 4;
    float4 a = *(const float4*)(x + (size_t)tok * CH + c);
    float4 p = *(const float4*)(proj + (size_t)src * CH + c);
    a.x += p.x; a.y += p.y; a.z += p.z; a.w += p.w;
    *(float4*)(out + (size_t)tok * CH + c) = a;

    float s  = a.x + a.y + a.z + a.w;
    float sq = a.x*a.x + a.y*a.y + a.z*a.z + a.w*a.w;
    #pragma unroll
    for (int off = 16; off; off >>= 1) {
        s  += __shfl_xor_sync(0xffffffffu, s, off);
        sq += __shfl_xor_sync(0xffffffffu, sq, off);
    }
    __shared__ float sh[8];
    int warp = tid >> 5, lane = tid & 31;
    if (lane == 0) { sh[warp] = s; sh[warp + 4] = sq; }
    __syncthreads();
    if (tid == 0) {
        float ts = sh[0] + sh[1] + sh[2] + sh[3];
        float tq = sh[4] + sh[5] + sh[6] + sh[7];
        float mean = ts * (1.0f / CH);
        float var = tq * (1.0f / CH) - mean * mean;
        sh[0] = mean; sh[1] = rsqrtf(var + 1e-5f);
    }
    __syncthreads();
    float mean = sh[0], inv = sh[1];
    float4 g4 = *(const float4*)(gamma + c);
    float4 b4 = *(const float4*)(beta + c);
    float o0 = (a.x - mean) * inv * g4.x + b4.x;
    float o1 = (a.y - mean) * inv * g4.y + b4.y;
    float o2 = (a.z - mean) * inv * g4.z + b4.z;
    float o3 = (a.w - mean) * inv * g4.w + b4.w;
    __half hh[4], ll[4];
    h_split(o0, hh[0], ll[0]); h_split(o1, hh[1], ll[1]);
    h_split(o2, hh[2], ll[2]); h_split(o3, hh[3], ll[3]);
    size_t base = (size_t)tok * CH + c;
    *(uint2*)(yh + base) = *(uint2*)hh;
    *(uint2*)(yl + base) = *(uint2*)ll;
}

// ---------------- launcher ----------------
extern "C" void kernel_launch(void* const* d_in, const int* in_sizes, int n_in,
                              void* d_out, int out_size)
{
    const float* x        = (const float*)d_in[0];
    const float* norm1_g  = (const float*)d_in[1];
    const float* norm1_b  = (const float*)d_in[2];
    const float* qkv_w    = (const float*)d_in[3];
    const float* qkv_b    = (const float*)d_in[4];
    const float* rel_tab  = (const float*)d_in[5];
    const float* proj_w   = (const float*)d_in[6];
    const float* proj_b   = (const float*)d_in[7];
    const float* norm2_g  = (const float*)d_in[8];
    const float* norm2_b  = (const float*)d_in[9];
    const float* fc1_w    = (const float*)d_in[10];
    const float* fc1_b    = (const float*)d_in[11];
    const float* fc2_w    = (const float*)d_in[12];
    const float* fc2_b    = (const float*)d_in[13];
    const int*   rel_idx  = (const int*)d_in[14];
    const float* attn_msk = (const float*)d_in[15];
    float* out = (float*)d_out;

    unsigned char *R1, *R2;
    cudaGetSymbolAddress((void**)&R1, g_R1);
    cudaGetSymbolAddress((void**)&R2, g_R2);
    __half *qkvT, *projT, *fc1T, *fc2T;
    cudaGetSymbolAddress((void**)&qkvT, g_qkvT);
    cudaGetSymbolAddress((void**)&projT, g_projT);
    cudaGetSymbolAddress((void**)&fc1T, g_fc1T);
    cudaGetSymbolAddress((void**)&fc2T, g_fc2T);

    float* qkv  = (float*)R1;
    float* proj = (float*)R1;
    __half* hid_h = (__half*)R1;
    __half* hid_l = (__half*)(R1 + (size_t)MTOK * HID * 2);
    __half* act_h = (__half*)R2;
    __half* act_l = (__half*)(R2 + (size_t)MTOK * CH * 2);

    cudaFuncSetAttribute(tgemm<0>, cudaFuncAttributeMaxDynamicSharedMemorySize, TGEMM_SMEM);
    cudaFuncSetAttribute(tgemm<1>, cudaFuncAttributeMaxDynamicSharedMemorySize, TGEMM_SMEM);
    cudaFuncSetAttribute(tgemm<2>, cudaFuncAttributeMaxDynamicSharedMemorySize, TGEMM_SMEM);

    // 0) weight transpose to fp16 [N,K]
    wsplit_kernel<<<dim3(3 * CH / 32, CH / 32), 256>>>(qkv_w,  qkvT, CH, 3 * CH);
    wsplit_kernel<<<dim3(CH / 32,     CH / 32), 256>>>(proj_w, projT, CH, CH);
    wsplit_kernel<<<dim3(HID / 32,    CH / 32), 256>>>(fc1_w,  fc1T, CH, HID);
    wsplit_kernel<<<dim3(CH / 32,    HID / 32), 256>>>(fc2_w,  fc2T, HID, CH);

    // 1) LN1 + shift + window partition
    ln_kernel<<<MTOK, 128>>>(x, norm1_g, norm1_b, act_h, act_l, 1);

    // 2) QKV GEMM (100352 x 1536 x 512)
    tgemm<0><<<dim3(3 * CH / 128, MTOK / 256), 512, TGEMM_SMEM>>>(
        act_h, act_l, qkvT, qkv_b, qkv, nullptr, nullptr, MTOK, 3 * CH, CH);

    // 3) attention
    attn_kernel<<<BN * NHEAD, 256>>>(qkv, rel_tab, rel_idx, attn_msk, act_h, act_l);

    // 4) proj GEMM (100352 x 512 x 512)
    tgemm<0><<<dim3(CH / 128, MTOK / 256), 512, TGEMM_SMEM>>>(
        act_h, act_l, projT, proj_b, proj, nullptr, nullptr, MTOK, CH, CH);

    // 5+6) reverse + residual -> d_out, fused LN2
    fuse2_kernel<<<MTOK, 128>>>(x, proj, norm2_g, norm2_b, out, act_h, act_l);

    // 7) FC1 + GELU (100352 x 2048 x 512)
    tgemm<1><<<dim3(HID / 128, MTOK / 256), 512, TGEMM_SMEM>>>(
        act_h, act_l, fc1T, fc1_b, nullptr, hid_h, hid_l, MTOK, HID, CH);

    // 8) FC2 + residual into d_out (100352 x 512 x 2048)
    tgemm<2><<<dim3(CH / 128, MTOK / 256), 512, TGEMM_SMEM>>>(
        hid_h, hid_l, fc2T, fc2_b, out, nullptr, nullptr, MTOK, CH, HID);

    (void)in_sizes; (void)n_in; (void)out_size;
}

// round 6
// speedup vs baseline: 3.6089x; 1.4491x over previous
#include <cuda_runtime.h>
#include <cuda_fp16.h>
#include <math.h>
#include <stdint.h>

// ---------------- problem constants ----------------
#define BATCH   32
#define HIMG    56
#define WIMG    56
#define CH      512
#define NHEAD   16
#define WS      7
#define SSH     3
#define HD      32
#define NWIN    49
#define NW_IMG  64
#define BN      (BATCH*NW_IMG)      // 2048 windows
#define MTOK    (BN*NWIN)           // 100352 tokens
#define HID     2048
#define SCALE   0.17677669529663687f

// ---------------- scratch ----------------
__device__ __align__(128) unsigned char g_R1[(size_t)MTOK * HID * 4];
__device__ __align__(128) unsigned char g_R2[(size_t)MTOK * CH * 2];

__device__ __align__(128) __half g_qkvT[3 * CH * CH];
__device__ __align__(128) __half g_projT[CH * CH];
__device__ __align__(128) __half g_fc1T[HID * CH];
__device__ __align__(128) __half g_fc2T[CH * HID];

// ---------------- helpers ----------------
__device__ __forceinline__ uint32_t smem_u32(const void* p) {
    uint32_t a;
    asm("{ .reg .u64 t; cvta.to.shared.u64 t, %1; cvt.u32.u64 %0, t; }" : "=r"(a) : "l"(p));
    return a;
}
#define CP16(dst, src) \
    asm volatile("cp.async.cg.shared.global [%0], [%1], 16;" :: "r"(dst), "l"(src))
#define CPCOMMIT() asm volatile("cp.async.commit_group;" ::: "memory")
#define CPWAIT1()  asm volatile("cp.async.wait_group 1;" ::: "memory")
#define CPWAIT0()  asm volatile("cp.async.wait_group 0;" ::: "memory")

#define LDSM4(r, a) \
    asm volatile("ldmatrix.sync.aligned.m8n8.x4.shared.b16 {%0,%1,%2,%3}, [%4];" \
        : "=r"((r)[0]), "=r"((r)[1]), "=r"((r)[2]), "=r"((r)[3]) : "r"(a))

__device__ __forceinline__ void mma_f16(float* c, const uint32_t* a, const uint32_t* b) {
    asm volatile("mma.sync.aligned.m16n8k16.row.col.f32.f16.f16.f32 "
        "{%0,%1,%2,%3}, {%4,%5,%6,%7}, {%8,%9}, {%0,%1,%2,%3};"
        : "+f"(c[0]), "+f"(c[1]), "+f"(c[2]), "+f"(c[3])
        : "r"(a[0]), "r"(a[1]), "r"(a[2]), "r"(a[3]), "r"(b[0]), "r"(b[1]));
}

// ---------------- weight transpose: W[K,N] -> Wt[N,K] fp16 ----------------
__global__ __launch_bounds__(256)
void wsplit_kernel(const float* __restrict__ W, __half* __restrict__ oh, int K, int N)
{
    __shared__ float t[32][33];
    int n0 = blockIdx.x * 32, k0 = blockIdx.y * 32;
    int tx = threadIdx.x & 31, ty = threadIdx.x >> 5;
    #pragma unroll
    for (int i = ty; i < 32; i += 8)
        t[i][tx] = W[(size_t)(k0 + i) * N + n0 + tx];
    __syncthreads();
    #pragma unroll
    for (int i = ty; i < 32; i += 8)
        oh[(size_t)(n0 + i) * K + k0 + tx] = __float2half_rn(t[tx][i]);
}

// ---------------- LayerNorm -> fp16 (mode1: shift+partition) ----------------
__global__ __launch_bounds__(128)
void ln_kernel(const float* __restrict__ x, const float* __restrict__ gamma,
               const float* __restrict__ beta, __half* __restrict__ oh, int mode)
{
    int tok = blockIdx.x;
    int src;
    if (mode == 1) {
        int w = tok / NWIN, n = tok - w * NWIN;
        int b = w >> 6, wi = w & 63;
        int wh = wi >> 3, ww = wi & 7;
        int i = n / WS, j = n - i * WS;
        int hp = wh * WS + i, wp = ww * WS + j;
        int hs = hp + SSH; if (hs >= HIMG) hs -= HIMG;
        int ws_ = wp + SSH; if (ws_ >= WIMG) ws_ -= WIMG;
        src = b * (HIMG * WIMG) + hs * WIMG + ws_;
    } else {
        src = tok;
    }
    int tid = threadIdx.x;
    int c = tid * 4;
    float4 v = *(const float4*)(x + (size_t)src * CH + c);
    float s  = v.x + v.y + v.z + v.w;
    float sq = v.x*v.x + v.y*v.y + v.z*v.z + v.w*v.w;
    #pragma unroll
    for (int off = 16; off; off >>= 1) {
        s  += __shfl_xor_sync(0xffffffffu, s, off);
        sq += __shfl_xor_sync(0xffffffffu, sq, off);
    }
    __shared__ float sh[8];
    int warp = tid >> 5, lane = tid & 31;
    if (lane == 0) { sh[warp] = s; sh[warp + 4] = sq; }
    __syncthreads();
    if (tid == 0) {
        float ts = sh[0] + sh[1] + sh[2] + sh[3];
        float tq = sh[4] + sh[5] + sh[6] + sh[7];
        float mean = ts * (1.0f / CH);
        float var = tq * (1.0f / CH) - mean * mean;
        sh[0] = mean; sh[1] = rsqrtf(var + 1e-5f);
    }
    __syncthreads();
    float mean = sh[0], inv = sh[1];
    float4 g4 = *(const float4*)(gamma + c);
    float4 b4 = *(const float4*)(beta + c);
    __half hh[4];
    hh[0] = __float2half_rn((v.x - mean) * inv * g4.x + b4.x);
    hh[1] = __float2half_rn((v.y - mean) * inv * g4.y + b4.y);
    hh[2] = __float2half_rn((v.z - mean) * inv * g4.z + b4.z);
    hh[3] = __float2half_rn((v.w - mean) * inv * g4.w + b4.w);
    *(uint2*)(oh + (size_t)tok * CH + c) = *(uint2*)hh;
}

// ---------------- fp16 GEMM via mma.sync ----------------
// C[M,N] = A[M,K] @ B^T (B stored [N,K]) + bias.
// Tile 256x128, 16 warps, warp tile 32x64. K-chunk 64 (128B rows), 2 stages.
#define STG_B   65536
#define STG_SZ  (32768 + 16384)
#define OFF_B   32768
#define TGEMM_SMEM (2 * STG_SZ)

template <int EPI>
__global__ void __launch_bounds__(512, 1)
tgemm(const __half* __restrict__ Ah, const __half* __restrict__ Bh,
      const float* __restrict__ bias, float* __restrict__ C,
      __half* __restrict__ Ch, int M, int N, int K)
{
    extern __shared__ __align__(128) char smem[];
    uint32_t sb = smem_u32(smem);
    int tid = threadIdx.x, wid = tid >> 5, lane = tid & 31;
    int m0 = blockIdx.y << 8, n0 = blockIdx.x << 7;
    int wm = wid & 7, wn = wid >> 3;

    // ---- loader coords ----
    int ar = tid >> 1, ac = (tid & 1) * 4;        // A: 256 rows, 4x16B per thread
    int br = tid >> 2, bc = (tid & 3) * 2;        // B: 128 rows, 2x16B per thread
    const char* gA = (const char*)(Ah + (size_t)(m0 + ar) * K) + ac * 16;
    const char* gB = (const char*)(Bh + (size_t)(n0 + br) * K) + bc * 16;
    uint32_t swA[4], swB[2];
    #pragma unroll
    for (int j = 0; j < 4; ++j)
        swA[j] = (uint32_t)(ar * 128 + (((ac + j) ^ (ar & 7)) << 4));
    #pragma unroll
    for (int j = 0; j < 2; ++j)
        swB[j] = (uint32_t)(br * 128 + (((bc + j) ^ (br & 7)) << 4));

    // ---- ldmatrix coords ----
    int arow = wm * 32 + (lane & 15);
    uint32_t aterm = (uint32_t)(arow * 128);
    int axor = arow & 7;
    int ac16 = lane >> 4;
    int brow = wn * 64 + ((lane >> 4) & 1) * 8 + (lane & 7);
    uint32_t bterm = (uint32_t)(brow * 128);
    int bxor = brow & 7;
    int bc16 = (lane >> 3) & 1;

    float acc[2][8][4];
    #pragma unroll
    for (int i = 0; i < 2; ++i)
        #pragma unroll
        for (int j = 0; j < 8; ++j)
            #pragma unroll
            for (int q = 0; q < 4; ++q) acc[i][j][q] = 0.0f;

    const int nch = K >> 6;

    // prologue
    {
        uint32_t s = sb;
        #pragma unroll
        for (int j = 0; j < 4; ++j) CP16(s + swA[j], gA + j * 16);
        #pragma unroll
        for (int j = 0; j < 2; ++j) CP16(s + OFF_B + swB[j], gB + j * 16);
        CPCOMMIT();
    }

    for (int c = 0; c < nch; ++c) {
        if (c + 1 < nch) {
            uint32_t s = sb + ((c + 1) & 1) * STG_SZ;
            size_t go = (size_t)(c + 1) * 128;
            #pragma unroll
            for (int j = 0; j < 4; ++j) CP16(s + swA[j], gA + go + j * 16);
            #pragma unroll
            for (int j = 0; j < 2; ++j) CP16(s + OFF_B + swB[j], gB + go + j * 16);
            CPCOMMIT();
            CPWAIT1();
        } else {
            CPWAIT0();
        }
        __syncthreads();

        uint32_t sS = sb + (c & 1) * STG_SZ;
        #pragma unroll
        for (int k16 = 0; k16 < 4; ++k16) {
            uint32_t ah[2][4];
            uint32_t aoff = aterm + ((uint32_t)((2 * k16 + ac16) ^ axor) << 4);
            LDSM4(ah[0], sS + aoff);
            LDSM4(ah[1], sS + aoff + 2048);
            uint32_t boff = bterm + ((uint32_t)((2 * k16 + bc16) ^ bxor) << 4);
            #pragma unroll
            for (int ng = 0; ng < 4; ++ng) {
                uint32_t bh[4];
                LDSM4(bh, sS + OFF_B + boff + ng * 2048);
                #pragma unroll
                for (int mt = 0; mt < 2; ++mt) {
                    mma_f16(acc[mt][2 * ng],     ah[mt], &bh[0]);
                    mma_f16(acc[mt][2 * ng + 1], ah[mt], &bh[2]);
                }
            }
        }
        __syncthreads();
    }

    // ---- epilogue ----
    int r0 = m0 + wm * 32 + (lane >> 2);
    int cb = n0 + wn * 64 + (lane & 3) * 2;
    #pragma unroll
    for (int mt = 0; mt < 2; ++mt) {
        #pragma unroll
        for (int n8 = 0; n8 < 8; ++n8) {
            int col = cb + n8 * 8;
            float2 bv = *(const float2*)(bias + col);
            #pragma unroll
            for (int rt = 0; rt < 2; ++rt) {
                int row = r0 + mt * 16 + rt * 8;
                float vx = acc[mt][n8][rt * 2]     + bv.x;
                float vy = acc[mt][n8][rt * 2 + 1] + bv.y;
                if (EPI == 0) {
                    float2 r = {vx, vy};
                    *(float2*)(C + (size_t)row * N + col) = r;
                } else if (EPI == 1) {
                    float gx = 0.5f * vx * (1.0f + erff(vx * 0.70710678118654752f));
                    float gy = 0.5f * vy * (1.0f + erff(vy * 0.70710678118654752f));
                    __half hh[2];
                    hh[0] = __float2half_rn(gx);
                    hh[1] = __float2half_rn(gy);
                    *(uint32_t*)(Ch + (size_t)row * N + col) = *(uint32_t*)hh;
                } else {
                    float* cp = C + (size_t)row * N + col;
                    float2 old = *(const float2*)cp;
                    float2 r = {vx + old.x, vy + old.y};
                    *(float2*)cp = r;
                }
            }
        }
    }
}

// ---------------- windowed attention (fp32 in, fp16 out) ----------------
__global__ __launch_bounds__(256)
void attn_kernel(const float* __restrict__ qkv, const float* __restrict__ table,
                 const int* __restrict__ relidx, const float* __restrict__ mask,
                 __half* __restrict__ oh)
{
    __shared__ float sq[NWIN * 33];
    __shared__ float sk[NWIN * 33];
    __shared__ float sv[NWIN * 33];
    __shared__ float ss[NWIN * 50];

    int bh = blockIdx.x;
    int b = bh >> 4, h = bh & 15;
    int tid = threadIdx.x;

    for (int idx = tid; idx < NWIN * HD; idx += 256) {
        int n = idx >> 5, d = idx & 31;
        size_t base = (size_t)(b * NWIN + n) * (3 * CH) + h * HD + d;
        sq[n * 33 + d] = qkv[base] * SCALE;
        sk[n * 33 + d] = qkv[base + CH];
        sv[n * 33 + d] = qkv[base + 2 * CH];
    }
    __syncthreads();

    int wi = b & 63;
    for (int idx = tid; idx < NWIN * NWIN; idx += 256) {
        int n = idx / NWIN, m = idx - n * NWIN;
        const float* qp = &sq[n * 33];
        const float* kp = &sk[m * 33];
        float acc = 0.0f;
        #pragma unroll
        for (int d = 0; d < HD; ++d) acc += qp[d] * kp[d];
        acc += table[relidx[idx] * NHEAD + h];
        acc += mask[(size_t)wi * (NWIN * NWIN) + idx];
        ss[n * 50 + m] = acc;
    }
    __syncthreads();

    int warp = tid >> 5, lane = tid & 31;
    for (int r = warp; r < NWIN; r += 8) {
        float v1 = ss[r * 50 + lane];
        float v2 = (lane + 32 < NWIN) ? ss[r * 50 + lane + 32] : -1e30f;
        float mx = fmaxf(v1, v2);
        #pragma unroll
        for (int off = 16; off; off >>= 1)
            mx = fmaxf(mx, __shfl_xor_sync(0xffffffffu, mx, off));
        float e1 = expf(v1 - mx);
        float e2 = (lane + 32 < NWIN) ? expf(v2 - mx) : 0.0f;
        float sum = e1 + e2;
        #pragma unroll
        for (int off = 16; off; off >>= 1)
            sum += __shfl_xor_sync(0xffffffffu, sum, off);
        float inv = 1.0f / sum;
        ss[r * 50 + lane] = e1 * inv;
        if (lane + 32 < NWIN) ss[r * 50 + lane + 32] = e2 * inv;
    }
    __syncthreads();

    for (int idx = tid; idx < NWIN * HD; idx += 256) {
        int n = idx >> 5, d = idx & 31;
        const float* pp = &ss[n * 50];
        float acc = 0.0f;
        #pragma unroll
        for (int m = 0; m < NWIN; ++m) acc += pp[m] * sv[m * 33 + d];
        oh[(size_t)(b * NWIN + n) * CH + h * HD + d] = __float2half_rn(acc);
    }
}

// ---------------- fused: reverse+roll+residual -> out, then LN2 -> yh ----------------
__global__ __launch_bounds__(128)
void fuse2_kernel(const float* __restrict__ x, const float* __restrict__ proj,
                  const float* __restrict__ gamma, const float* __restrict__ beta,
                  float* __restrict__ out, __half* __restrict__ yh)
{
    int tok = blockIdx.x;
    int b = tok / (HIMG * WIMG);
    int rem = tok - b * (HIMG * WIMG);
    int hp0 = rem / WIMG, wp0 = rem - hp0 * WIMG;
    int hp = hp0 - SSH; if (hp < 0) hp += HIMG;
    int wp = wp0 - SSH; if (wp < 0) wp += WIMG;
    int wh = hp / WS, i = hp - wh * WS;
    int ww = wp / WS, j = wp - ww * WS;
    int src = (b * NW_IMG + wh * 8 + ww) * NWIN + i * WS + j;

    int tid = threadIdx.x;
    int c = tid * 4;
    float4 a = *(const float4*)(x + (size_t)tok * CH + c);
    float4 p = *(const float4*)(proj + (size_t)src * CH + c);
    a.x += p.x; a.y += p.y; a.z += p.z; a.w += p.w;
    *(float4*)(out + (size_t)tok * CH + c) = a;

    float s  = a.x + a.y + a.z + a.w;
    float sq = a.x*a.x + a.y*a.y + a.z*a.z + a.w*a.w;
    #pragma unroll
    for (int off = 16; off; off >>= 1) {
        s  += __shfl_xor_sync(0xffffffffu, s, off);
        sq += __shfl_xor_sync(0xffffffffu, sq, off);
    }
    __shared__ float sh[8];
    int warp = tid >> 5, lane = tid & 31;
    if (lane == 0) { sh[warp] = s; sh[warp + 4] = sq; }
    __syncthreads();
    if (tid == 0) {
        float ts = sh[0] + sh[1] + sh[2] + sh[3];
        float tq = sh[4] + sh[5] + sh[6] + sh[7];
        float mean = ts * (1.0f / CH);
        float var = tq * (1.0f / CH) - mean * mean;
        sh[0] = mean; sh[1] = rsqrtf(var + 1e-5f);
    }
    __syncthreads();
    float mean = sh[0], inv = sh[1];
    float4 g4 = *(const float4*)(gamma + c);
    float4 b4 = *(const float4*)(beta + c);
    __half hh[4];
    hh[0] = __float2half_rn((a.x - mean) * inv * g4.x + b4.x);
    hh[1] = __float2half_rn((a.y - mean) * inv * g4.y + b4.y);
    hh[2] = __float2half_rn((a.z - mean) * inv * g4.z + b4.z);
    hh[3] = __float2half_rn((a.w - mean) * inv * g4.w + b4.w);
    *(uint2*)(yh + (size_t)tok * CH + c) = *(uint2*)hh;
}

// ---------------- launcher ----------------
extern "C" void kernel_launch(void* const* d_in, const int* in_sizes, int n_in,
                              void* d_out, int out_size)
{
    const float* x        = (const float*)d_in[0];
    const float* norm1_g  = (const float*)d_in[1];
    const float* norm1_b  = (const float*)d_in[2];
    const float* qkv_w    = (const float*)d_in[3];
    const float* qkv_b    = (const float*)d_in[4];
    const float* rel_tab  = (const float*)d_in[5];
    const float* proj_w   = (const float*)d_in[6];
    const float* proj_b   = (const float*)d_in[7];
    const float* norm2_g  = (const float*)d_in[8];
    const float* norm2_b  = (const float*)d_in[9];
    const float* fc1_w    = (const float*)d_in[10];
    const float* fc1_b    = (const float*)d_in[11];
    const float* fc2_w    = (const float*)d_in[12];
    const float* fc2_b    = (const float*)d_in[13];
    const int*   rel_idx  = (const int*)d_in[14];
    const float* attn_msk = (const float*)d_in[15];
    float* out = (float*)d_out;

    unsigned char *R1, *R2;
    cudaGetSymbolAddress((void**)&R1, g_R1);
    cudaGetSymbolAddress((void**)&R2, g_R2);
    __half *qkvT, *projT, *fc1T, *fc2T;
    cudaGetSymbolAddress((void**)&qkvT, g_qkvT);
    cudaGetSymbolAddress((void**)&projT, g_projT);
    cudaGetSymbolAddress((void**)&fc1T, g_fc1T);
    cudaGetSymbolAddress((void**)&fc2T, g_fc2T);

    float* qkv  = (float*)R1;
    float* proj = (float*)R1;
    __half* hid = (__half*)R1;
    __half* act = (__half*)R2;     // wins -> o -> y

    cudaFuncSetAttribute(tgemm<0>, cudaFuncAttributeMaxDynamicSharedMemorySize, TGEMM_SMEM);
    cudaFuncSetAttribute(tgemm<1>, cudaFuncAttributeMaxDynamicSharedMemorySize, TGEMM_SMEM);
    cudaFuncSetAttribute(tgemm<2>, cudaFuncAttributeMaxDynamicSharedMemorySize, TGEMM_SMEM);

    // 0) weight transpose to fp16 [N,K]
    wsplit_kernel<<<dim3(3 * CH / 32, CH / 32), 256>>>(qkv_w,  qkvT, CH, 3 * CH);
    wsplit_kernel<<<dim3(CH / 32,     CH / 32), 256>>>(proj_w, projT, CH, CH);
    wsplit_kernel<<<dim3(HID / 32,    CH / 32), 256>>>(fc1_w,  fc1T, CH, HID);
    wsplit_kernel<<<dim3(CH / 32,    HID / 32), 256>>>(fc2_w,  fc2T, HID, CH);

    // 1) LN1 + shift + window partition
    ln_kernel<<<MTOK, 128>>>(x, norm1_g, norm1_b, act, 1);

    // 2) QKV GEMM (100352 x 1536 x 512)
    tgemm<0><<<dim3(3 * CH / 128, MTOK / 256), 512, TGEMM_SMEM>>>(
        act, qkvT, qkv_b, qkv, nullptr, MTOK, 3 * CH, CH);

    // 3) attention
    attn_kernel<<<BN * NHEAD, 256>>>(qkv, rel_tab, rel_idx, attn_msk, act);

    // 4) proj GEMM (100352 x 512 x 512)
    tgemm<0><<<dim3(CH / 128, MTOK / 256), 512, TGEMM_SMEM>>>(
        act, projT, proj_b, proj, nullptr, MTOK, CH, CH);

    // 5+6) reverse + residual -> d_out, fused LN2
    fuse2_kernel<<<MTOK, 128>>>(x, proj, norm2_g, norm2_b, out, act);

    // 7) FC1 + GELU (100352 x 2048 x 512)
    tgemm<1><<<dim3(HID / 128, MTOK / 256), 512, TGEMM_SMEM>>>(
        act, fc1T, fc1_b, nullptr, hid, MTOK, HID, CH);

    // 8) FC2 + residual into d_out (100352 x 512 x 2048)
    tgemm<2><<<dim3(CH / 128, MTOK / 256), 512, TGEMM_SMEM>>>(
        hid, fc2T, fc2_b, out, nullptr, MTOK, CH, HID);

    (void)in_sizes; (void)n_in; (void)out_size;
}

// round 7
// speedup vs baseline: 3.8351x; 1.0627x over previous
#include <cuda_runtime.h>
#include <cuda_fp16.h>
#include <math.h>
#include <stdint.h>

// ---------------- problem constants ----------------
#define BATCH   32
#define HIMG    56
#define WIMG    56
#define CH      512
#define NHEAD   16
#define WS      7
#define SSH     3
#define HD      32
#define NWIN    49
#define NW_IMG  64
#define BN      (BATCH*NW_IMG)      // 2048 windows
#define MTOK    (BN*NWIN)           // 100352 tokens
#define HID     2048
#define SCALE   0.17677669529663687f

// ---------------- scratch ----------------
__device__ __align__(128) unsigned char g_R1[(size_t)MTOK * HID * 4];
__device__ __align__(128) unsigned char g_R2[(size_t)MTOK * CH * 2];

__device__ __align__(128) __half g_qkvT[3 * CH * CH];
__device__ __align__(128) __half g_projT[CH * CH];
__device__ __align__(128) __half g_fc1T[HID * CH];
__device__ __align__(128) __half g_fc2T[CH * HID];

// ---------------- helpers ----------------
__device__ __forceinline__ uint32_t smem_u32(const void* p) {
    uint32_t a;
    asm("{ .reg .u64 t; cvta.to.shared.u64 t, %1; cvt.u32.u64 %0, t; }" : "=r"(a) : "l"(p));
    return a;
}
#define CP16(dst, src) \
    asm volatile("cp.async.cg.shared.global [%0], [%1], 16;" :: "r"(dst), "l"(src))
#define CPCOMMIT() asm volatile("cp.async.commit_group;" ::: "memory")
#define CPWAIT1()  asm volatile("cp.async.wait_group 1;" ::: "memory")
#define CPWAIT0()  asm volatile("cp.async.wait_group 0;" ::: "memory")

#define LDSM4(r, a) \
    asm volatile("ldmatrix.sync.aligned.m8n8.x4.shared.b16 {%0,%1,%2,%3}, [%4];" \
        : "=r"((r)[0]), "=r"((r)[1]), "=r"((r)[2]), "=r"((r)[3]) : "r"(a))

__device__ __forceinline__ void mma_f16(float* c, const uint32_t* a, const uint32_t* b) {
    asm volatile("mma.sync.aligned.m16n8k16.row.col.f32.f16.f16.f32 "
        "{%0,%1,%2,%3}, {%4,%5,%6,%7}, {%8,%9}, {%0,%1,%2,%3};"
        : "+f"(c[0]), "+f"(c[1]), "+f"(c[2]), "+f"(c[3])
        : "r"(a[0]), "r"(a[1]), "r"(a[2]), "r"(a[3]), "r"(b[0]), "r"(b[1]));
}

// ---------------- weight transpose: W[K,N] -> Wt[N,K] fp16 ----------------
__global__ __launch_bounds__(256)
void wsplit_kernel(const float* __restrict__ W, __half* __restrict__ oh, int K, int N)
{
    __shared__ float t[32][33];
    int n0 = blockIdx.x * 32, k0 = blockIdx.y * 32;
    int tx = threadIdx.x & 31, ty = threadIdx.x >> 5;
    #pragma unroll
    for (int i = ty; i < 32; i += 8)
        t[i][tx] = W[(size_t)(k0 + i) * N + n0 + tx];
    __syncthreads();
    #pragma unroll
    for (int i = ty; i < 32; i += 8)
        oh[(size_t)(n0 + i) * K + k0 + tx] = __float2half_rn(t[tx][i]);
}

// ---------------- LayerNorm -> fp16 (mode1: shift+partition) ----------------
__global__ __launch_bounds__(128)
void ln_kernel(const float* __restrict__ x, const float* __restrict__ gamma,
               const float* __restrict__ beta, __half* __restrict__ oh, int mode)
{
    int tok = blockIdx.x;
    int src;
    if (mode == 1) {
        int w = tok / NWIN, n = tok - w * NWIN;
        int b = w >> 6, wi = w & 63;
        int wh = wi >> 3, ww = wi & 7;
        int i = n / WS, j = n - i * WS;
        int hp = wh * WS + i, wp = ww * WS + j;
        int hs = hp + SSH; if (hs >= HIMG) hs -= HIMG;
        int ws_ = wp + SSH; if (ws_ >= WIMG) ws_ -= WIMG;
        src = b * (HIMG * WIMG) + hs * WIMG + ws_;
    } else {
        src = tok;
    }
    int tid = threadIdx.x;
    int c = tid * 4;
    float4 v = *(const float4*)(x + (size_t)src * CH + c);
    float s  = v.x + v.y + v.z + v.w;
    float sq = v.x*v.x + v.y*v.y + v.z*v.z + v.w*v.w;
    #pragma unroll
    for (int off = 16; off; off >>= 1) {
        s  += __shfl_xor_sync(0xffffffffu, s, off);
        sq += __shfl_xor_sync(0xffffffffu, sq, off);
    }
    __shared__ float sh[8];
    int warp = tid >> 5, lane = tid & 31;
    if (lane == 0) { sh[warp] = s; sh[warp + 4] = sq; }
    __syncthreads();
    if (tid == 0) {
        float ts = sh[0] + sh[1] + sh[2] + sh[3];
        float tq = sh[4] + sh[5] + sh[6] + sh[7];
        float mean = ts * (1.0f / CH);
        float var = tq * (1.0f / CH) - mean * mean;
        sh[0] = mean; sh[1] = rsqrtf(var + 1e-5f);
    }
    __syncthreads();
    float mean = sh[0], inv = sh[1];
    float4 g4 = *(const float4*)(gamma + c);
    float4 b4 = *(const float4*)(beta + c);
    __half hh[4];
    hh[0] = __float2half_rn((v.x - mean) * inv * g4.x + b4.x);
    hh[1] = __float2half_rn((v.y - mean) * inv * g4.y + b4.y);
    hh[2] = __float2half_rn((v.z - mean) * inv * g4.z + b4.z);
    hh[3] = __float2half_rn((v.w - mean) * inv * g4.w + b4.w);
    *(uint2*)(oh + (size_t)tok * CH + c) = *(uint2*)hh;
}

// ---------------- fp16 GEMM via mma.sync ----------------
// C[M,N] = A[M,K] @ B^T (B stored [N,K]) + bias.
// Tile 256x128, 16 warps, warp tile 32x64. K-chunk 64 (128B rows), 3 stages.
// EPI: 0 f32 store, 1 GELU->fp16, 2 f32 RMW add, 3 fp16 store
#define OFF_B   32768
#define STG_SZ  49152
#define TGEMM_SMEM (3 * STG_SZ)

template <int EPI>
__global__ void __launch_bounds__(512, 1)
tgemm(const __half* __restrict__ Ah, const __half* __restrict__ Bh,
      const float* __restrict__ bias, float* __restrict__ C,
      __half* __restrict__ Ch, int M, int N, int K)
{
    extern __shared__ __align__(128) char smem[];
    uint32_t sb = smem_u32(smem);
    int tid = threadIdx.x, wid = tid >> 5, lane = tid & 31;
    int m0 = blockIdx.y << 8, n0 = blockIdx.x << 7;
    int wm = wid & 7, wn = wid >> 3;

    // ---- loader coords ----
    int ar = tid >> 1, ac = (tid & 1) * 4;
    int br = tid >> 2, bc = (tid & 3) * 2;
    const char* gA = (const char*)(Ah + (size_t)(m0 + ar) * K) + ac * 16;
    const char* gB = (const char*)(Bh + (size_t)(n0 + br) * K) + bc * 16;
    uint32_t swA[4], swB[2];
    #pragma unroll
    for (int j = 0; j < 4; ++j)
        swA[j] = (uint32_t)(ar * 128 + (((ac + j) ^ (ar & 7)) << 4));
    #pragma unroll
    for (int j = 0; j < 2; ++j)
        swB[j] = (uint32_t)(br * 128 + (((bc + j) ^ (br & 7)) << 4));

    // ---- ldmatrix coords ----
    int arow = wm * 32 + (lane & 15);
    uint32_t aterm = (uint32_t)(arow * 128);
    int axor = arow & 7;
    int ac16 = lane >> 4;
    int brow = wn * 64 + ((lane >> 4) & 1) * 8 + (lane & 7);
    uint32_t bterm = (uint32_t)(brow * 128);
    int bxor = brow & 7;
    int bc16 = (lane >> 3) & 1;

    float acc[2][8][4];
    #pragma unroll
    for (int i = 0; i < 2; ++i)
        #pragma unroll
        for (int j = 0; j < 8; ++j)
            #pragma unroll
            for (int q = 0; q < 4; ++q) acc[i][j][q] = 0.0f;

    const int nch = K >> 6;

    // prologue: issue chunks 0 and 1
    #pragma unroll
    for (int pc = 0; pc < 2; ++pc) {
        uint32_t s = sb + pc * STG_SZ;
        size_t go = (size_t)pc * 128;
        #pragma unroll
        for (int j = 0; j < 4; ++j) CP16(s + swA[j], gA + go + j * 16);
        #pragma unroll
        for (int j = 0; j < 2; ++j) CP16(s + OFF_B + swB[j], gB + go + j * 16);
        CPCOMMIT();
    }

    int buf = 0;
    for (int c = 0; c < nch; ++c) {
        if (c + 1 < nch) { CPWAIT1(); } else { CPWAIT0(); }
        __syncthreads();
        // issue chunk c+2 into the buffer chunk c-1 used (all reads done)
        if (c + 2 < nch) {
            int b2 = buf + 2; if (b2 >= 3) b2 -= 3;
            uint32_t s = sb + b2 * STG_SZ;
            size_t go = (size_t)(c + 2) * 128;
            #pragma unroll
            for (int j = 0; j < 4; ++j) CP16(s + swA[j], gA + go + j * 16);
            #pragma unroll
            for (int j = 0; j < 2; ++j) CP16(s + OFF_B + swB[j], gB + go + j * 16);
            CPCOMMIT();
        } else {
            CPCOMMIT();   // keep group counting uniform
        }

        uint32_t sS = sb + buf * STG_SZ;
        #pragma unroll
        for (int k16 = 0; k16 < 4; ++k16) {
            uint32_t ah[2][4];
            uint32_t aoff = aterm + ((uint32_t)((2 * k16 + ac16) ^ axor) << 4);
            LDSM4(ah[0], sS + aoff);
            LDSM4(ah[1], sS + aoff + 2048);
            uint32_t boff = bterm + ((uint32_t)((2 * k16 + bc16) ^ bxor) << 4);
            #pragma unroll
            for (int ng = 0; ng < 4; ++ng) {
                uint32_t bh[4];
                LDSM4(bh, sS + OFF_B + boff + ng * 2048);
                #pragma unroll
                for (int mt = 0; mt < 2; ++mt) {
                    mma_f16(acc[mt][2 * ng],     ah[mt], &bh[0]);
                    mma_f16(acc[mt][2 * ng + 1], ah[mt], &bh[2]);
                }
            }
        }
        if (++buf == 3) buf = 0;
    }

    // ---- epilogue ----
    int r0 = m0 + wm * 32 + (lane >> 2);
    int cb = n0 + wn * 64 + (lane & 3) * 2;
    #pragma unroll
    for (int mt = 0; mt < 2; ++mt) {
        #pragma unroll
        for (int n8 = 0; n8 < 8; ++n8) {
            int col = cb + n8 * 8;
            float2 bv = *(const float2*)(bias + col);
            #pragma unroll
            for (int rt = 0; rt < 2; ++rt) {
                int row = r0 + mt * 16 + rt * 8;
                float vx = acc[mt][n8][rt * 2]     + bv.x;
                float vy = acc[mt][n8][rt * 2 + 1] + bv.y;
                if (EPI == 0) {
                    float2 r = {vx, vy};
                    *(float2*)(C + (size_t)row * N + col) = r;
                } else if (EPI == 1) {
                    float gx = 0.5f * vx * (1.0f + erff(vx * 0.70710678118654752f));
                    float gy = 0.5f * vy * (1.0f + erff(vy * 0.70710678118654752f));
                    __half hh[2];
                    hh[0] = __float2half_rn(gx);
                    hh[1] = __float2half_rn(gy);
                    *(uint32_t*)(Ch + (size_t)row * N + col) = *(uint32_t*)hh;
                } else if (EPI == 2) {
                    float* cp = C + (size_t)row * N + col;
                    float2 old = *(const float2*)cp;
                    float2 r = {vx + old.x, vy + old.y};
                    *(float2*)cp = r;
                } else {
                    __half hh[2];
                    hh[0] = __float2half_rn(vx);
                    hh[1] = __float2half_rn(vy);
                    *(uint32_t*)(Ch + (size_t)row * N + col) = *(uint32_t*)hh;
                }
            }
        }
    }
}

// ---------------- windowed attention (fp16 in, fp16 out) ----------------
__global__ __launch_bounds__(256)
void attn_kernel(const __half* __restrict__ qkv, const float* __restrict__ table,
                 const int* __restrict__ relidx, const float* __restrict__ mask,
                 __half* __restrict__ oh)
{
    __shared__ float sq[NWIN * 36];
    __shared__ float sk[NWIN * 36];
    __shared__ float sv[NWIN * 36];
    __shared__ float ss[NWIN * 52];

    int bh = blockIdx.x;
    int b = bh >> 4, h = bh & 15;
    int tid = threadIdx.x;

    // load q/k/v (fp16 -> fp32 smem)
    for (int idx = tid; idx < NWIN * 16; idx += 256) {
        int n = idx >> 4, d = (idx & 15) * 2;
        size_t base = (size_t)(b * NWIN + n) * (3 * CH) + h * HD + d;
        float2 q2 = __half22float2(*(const __half2*)(qkv + base));
        float2 k2 = __half22float2(*(const __half2*)(qkv + base + CH));
        float2 v2 = __half22float2(*(const __half2*)(qkv + base + 2 * CH));
        sq[n * 36 + d] = q2.x * SCALE; sq[n * 36 + d + 1] = q2.y * SCALE;
        sk[n * 36 + d] = k2.x;         sk[n * 36 + d + 1] = k2.y;
        sv[n * 36 + d] = v2.x;         sv[n * 36 + d + 1] = v2.y;
    }
    __syncthreads();

    int wi = b & 63;
    for (int idx = tid; idx < NWIN * NWIN; idx += 256) {
        int n = idx / NWIN, m = idx - n * NWIN;
        const float4* qp = (const float4*)&sq[n * 36];
        const float4* kp = (const float4*)&sk[m * 36];
        float acc = 0.0f;
        #pragma unroll
        for (int t = 0; t < 8; ++t) {
            float4 a = qp[t], c4 = kp[t];
            acc += a.x * c4.x + a.y * c4.y + a.z * c4.z + a.w * c4.w;
        }
        acc += table[relidx[idx] * NHEAD + h];
        acc += mask[(size_t)wi * (NWIN * NWIN) + idx];
        ss[n * 52 + m] = acc;
    }
    __syncthreads();

    int warp = tid >> 5, lane = tid & 31;
    for (int r = warp; r < NWIN; r += 8) {
        float v1 = ss[r * 52 + lane];
        float v2 = (lane + 32 < NWIN) ? ss[r * 52 + lane + 32] : -1e30f;
        float mx = fmaxf(v1, v2);
        #pragma unroll
        for (int off = 16; off; off >>= 1)
            mx = fmaxf(mx, __shfl_xor_sync(0xffffffffu, mx, off));
        float e1 = expf(v1 - mx);
        float e2 = (lane + 32 < NWIN) ? expf(v2 - mx) : 0.0f;
        float sum = e1 + e2;
        #pragma unroll
        for (int off = 16; off; off >>= 1)
            sum += __shfl_xor_sync(0xffffffffu, sum, off);
        float inv = 1.0f / sum;
        ss[r * 52 + lane] = e1 * inv;
        if (lane + 32 < NWIN) ss[r * 52 + lane + 32] = e2 * inv;
    }
    __syncthreads();

    for (int idx = tid; idx < NWIN * HD; idx += 256) {
        int n = idx >> 5, d = idx & 31;
        const float* pp = &ss[n * 52];
        float acc = 0.0f;
        #pragma unroll
        for (int m = 0; m < NWIN; ++m) acc += pp[m] * sv[m * 36 + d];
        oh[(size_t)(b * NWIN + n) * CH + h * HD + d] = __float2half_rn(acc);
    }
}

// ---------------- fused: reverse+roll+residual -> out, then LN2 -> yh ----------------
__global__ __launch_bounds__(128)
void fuse2_kernel(const float* __restrict__ x, const float* __restrict__ proj,
                  const float* __restrict__ gamma, const float* __restrict__ beta,
                  float* __restrict__ out, __half* __restrict__ yh)
{
    int tok = blockIdx.x;
    int b = tok / (HIMG * WIMG);
    int rem = tok - b * (HIMG * WIMG);
    int hp0 = rem / WIMG, wp0 = rem - hp0 * WIMG;
    int hp = hp0 - SSH; if (hp < 0) hp += HIMG;
    int wp = wp0 - SSH; if (wp < 0) wp += WIMG;
    int wh = hp / WS, i = hp - wh * WS;
    int ww = wp / WS, j = wp - ww * WS;
    int src = (b * NW_IMG + wh * 8 + ww) * NWIN + i * WS + j;

    int tid = threadIdx.x;
    int c = tid * 4;
    float4 a = *(const float4*)(x + (size_t)tok * CH + c);
    float4 p = *(const float4*)(proj + (size_t)src * CH + c);
    a.x += p.x; a.y += p.y; a.z += p.z; a.w += p.w;
    *(float4*)(out + (size_t)tok * CH + c) = a;

    float s  = a.x + a.y + a.z + a.w;
    float sq = a.x*a.x + a.y*a.y + a.z*a.z + a.w*a.w;
    #pragma unroll
    for (int off = 16; off; off >>= 1) {
        s  += __shfl_xor_sync(0xffffffffu, s, off);
        sq += __shfl_xor_sync(0xffffffffu, sq, off);
    }
    __shared__ float sh[8];
    int warp = tid >> 5, lane = tid & 31;
    if (lane == 0) { sh[warp] = s; sh[warp + 4] = sq; }
    __syncthreads();
    if (tid == 0) {
        float ts = sh[0] + sh[1] + sh[2] + sh[3];
        float tq = sh[4] + sh[5] + sh[6] + sh[7];
        float mean = ts * (1.0f / CH);
        float var = tq * (1.0f / CH) - mean * mean;
        sh[0] = mean; sh[1] = rsqrtf(var + 1e-5f);
    }
    __syncthreads();
    float mean = sh[0], inv = sh[1];
    float4 g4 = *(const float4*)(gamma + c);
    float4 b4 = *(const float4*)(beta + c);
    __half hh[4];
    hh[0] = __float2half_rn((a.x - mean) * inv * g4.x + b4.x);
    hh[1] = __float2half_rn((a.y - mean) * inv * g4.y + b4.y);
    hh[2] = __float2half_rn((a.z - mean) * inv * g4.z + b4.z);
    hh[3] = __float2half_rn((a.w - mean) * inv * g4.w + b4.w);
    *(uint2*)(yh + (size_t)tok * CH + c) = *(uint2*)hh;
}

// ---------------- launcher ----------------
extern "C" void kernel_launch(void* const* d_in, const int* in_sizes, int n_in,
                              void* d_out, int out_size)
{
    const float* x        = (const float*)d_in[0];
    const float* norm1_g  = (const float*)d_in[1];
    const float* norm1_b  = (const float*)d_in[2];
    const float* qkv_w    = (const float*)d_in[3];
    const float* qkv_b    = (const float*)d_in[4];
    const float* rel_tab  = (const float*)d_in[5];
    const float* proj_w   = (const float*)d_in[6];
    const float* proj_b   = (const float*)d_in[7];
    const float* norm2_g  = (const float*)d_in[8];
    const float* norm2_b  = (const float*)d_in[9];
    const float* fc1_w    = (const float*)d_in[10];
    const float* fc1_b    = (const float*)d_in[11];
    const float* fc2_w    = (const float*)d_in[12];
    const float* fc2_b    = (const float*)d_in[13];
    const int*   rel_idx  = (const int*)d_in[14];
    const float* attn_msk = (const float*)d_in[15];
    float* out = (float*)d_out;

    unsigned char *R1, *R2;
    cudaGetSymbolAddress((void**)&R1, g_R1);
    cudaGetSymbolAddress((void**)&R2, g_R2);
    __half *qkvT, *projT, *fc1T, *fc2T;
    cudaGetSymbolAddress((void**)&qkvT, g_qkvT);
    cudaGetSymbolAddress((void**)&projT, g_projT);
    cudaGetSymbolAddress((void**)&fc1T, g_fc1T);
    cudaGetSymbolAddress((void**)&fc2T, g_fc2T);

    __half* qkv = (__half*)R1;               // fp16 now (308MB)
    float* proj = (float*)(R1 + (size_t)MTOK * 3 * CH * 2);  // fp32 205MB, disjoint
    __half* hid = (__half*)R1;               // reused after proj consumed? careful:
    // hid (411MB fp16) overlaps qkv region (qkv dead after attention) - OK.
    __half* act = (__half*)R2;               // wins -> o -> y

    cudaFuncSetAttribute(tgemm<0>, cudaFuncAttributeMaxDynamicSharedMemorySize, TGEMM_SMEM);
    cudaFuncSetAttribute(tgemm<1>, cudaFuncAttributeMaxDynamicSharedMemorySize, TGEMM_SMEM);
    cudaFuncSetAttribute(tgemm<2>, cudaFuncAttributeMaxDynamicSharedMemorySize, TGEMM_SMEM);
    cudaFuncSetAttribute(tgemm<3>, cudaFuncAttributeMaxDynamicSharedMemorySize, TGEMM_SMEM);

    // 0) weight transpose to fp16 [N,K]
    wsplit_kernel<<<dim3(3 * CH / 32, CH / 32), 256>>>(qkv_w,  qkvT, CH, 3 * CH);
    wsplit_kernel<<<dim3(CH / 32,     CH / 32), 256>>>(proj_w, projT, CH, CH);
    wsplit_kernel<<<dim3(HID / 32,    CH / 32), 256>>>(fc1_w,  fc1T, CH, HID);
    wsplit_kernel<<<dim3(CH / 32,    HID / 32), 256>>>(fc2_w,  fc2T, HID, CH);

    // 1) LN1 + shift + window partition
    ln_kernel<<<MTOK, 128>>>(x, norm1_g, norm1_b, act, 1);

    // 2) QKV GEMM (100352 x 1536 x 512) -> fp16
    tgemm<3><<<dim3(3 * CH / 128, MTOK / 256), 512, TGEMM_SMEM>>>(
        act, qkvT, qkv_b, nullptr, qkv, MTOK, 3 * CH, CH);

    // 3) attention (fp16 qkv in, fp16 o out)
    attn_kernel<<<BN * NHEAD, 256>>>(qkv, rel_tab, rel_idx, attn_msk, act);

    // 4) proj GEMM (100352 x 512 x 512) -> fp32
    tgemm<0><<<dim3(CH / 128, MTOK / 256), 512, TGEMM_SMEM>>>(
        act, projT, proj_b, proj, nullptr, MTOK, CH, CH);

    // 5+6) reverse + residual -> d_out, fused LN2
    fuse2_kernel<<<MTOK, 128>>>(x, proj, norm2_g, norm2_b, out, act);

    // 7) FC1 + GELU (100352 x 2048 x 512) -> fp16 hid
    tgemm<1><<<dim3(HID / 128, MTOK / 256), 512, TGEMM_SMEM>>>(
        act, fc1T, fc1_b, nullptr, hid, MTOK, HID, CH);

    // 8) FC2 + residual into d_out (100352 x 512 x 2048)
    tgemm<2><<<dim3(CH / 128, MTOK / 256), 512, TGEMM_SMEM>>>(
        hid, fc2T, fc2_b, out, nullptr, MTOK, CH, HID);

    (void)in_sizes; (void)n_in; (void)out_size;
}

// round 8
// speedup vs baseline: 3.8358x; 1.0002x over previous
#include <cuda_runtime.h>
#include <cuda_fp16.h>
#include <math.h>
#include <stdint.h>

// ---------------- problem constants ----------------
#define BATCH   32
#define HIMG    56
#define WIMG    56
#define CH      512
#define NHEAD   16
#define WS      7
#define SSH     3
#define HD      32
#define NWIN    49
#define NW_IMG  64
#define BN      (BATCH*NW_IMG)      // 2048 windows
#define MTOK    (BN*NWIN)           // 100352 tokens
#define HID     2048
#define SCALE   0.17677669529663687f

// ---------------- scratch ----------------
__device__ __align__(128) unsigned char g_R1[(size_t)MTOK * HID * 4];
__device__ __align__(128) unsigned char g_R2[(size_t)MTOK * CH * 2];

__device__ __align__(128) __half g_qkvT[3 * CH * CH];
__device__ __align__(128) __half g_projT[CH * CH];
__device__ __align__(128) __half g_fc1T[HID * CH];
__device__ __align__(128) __half g_fc2T[CH * HID];

// ---------------- helpers ----------------
__device__ __forceinline__ uint32_t smem_u32(const void* p) {
    uint32_t a;
    asm("{ .reg .u64 t; cvta.to.shared.u64 t, %1; cvt.u32.u64 %0, t; }" : "=r"(a) : "l"(p));
    return a;
}
#define CP16(dst, src) \
    asm volatile("cp.async.cg.shared.global [%0], [%1], 16;" :: "r"(dst), "l"(src))
#define CPCOMMIT() asm volatile("cp.async.commit_group;" ::: "memory")
#define CPWAIT1()  asm volatile("cp.async.wait_group 1;" ::: "memory")
#define CPWAIT0()  asm volatile("cp.async.wait_group 0;" ::: "memory")

#define LDSM4(r, a) \
    asm volatile("ldmatrix.sync.aligned.m8n8.x4.shared.b16 {%0,%1,%2,%3}, [%4];" \
        : "=r"((r)[0]), "=r"((r)[1]), "=r"((r)[2]), "=r"((r)[3]) : "r"(a))

__device__ __forceinline__ void mma_f16(float* c, const uint32_t* a, const uint32_t* b) {
    asm volatile("mma.sync.aligned.m16n8k16.row.col.f32.f16.f16.f32 "
        "{%0,%1,%2,%3}, {%4,%5,%6,%7}, {%8,%9}, {%0,%1,%2,%3};"
        : "+f"(c[0]), "+f"(c[1]), "+f"(c[2]), "+f"(c[3])
        : "r"(a[0]), "r"(a[1]), "r"(a[2]), "r"(a[3]), "r"(b[0]), "r"(b[1]));
}

// ---------------- weight transpose: W[K,N] -> Wt[N,K] fp16 ----------------
__global__ __launch_bounds__(256)
void wsplit_kernel(const float* __restrict__ W, __half* __restrict__ oh, int K, int N)
{
    __shared__ float t[32][33];
    int n0 = blockIdx.x * 32, k0 = blockIdx.y * 32;
    int tx = threadIdx.x & 31, ty = threadIdx.x >> 5;
    #pragma unroll
    for (int i = ty; i < 32; i += 8)
        t[i][tx] = W[(size_t)(k0 + i) * N + n0 + tx];
    __syncthreads();
    #pragma unroll
    for (int i = ty; i < 32; i += 8)
        oh[(size_t)(n0 + i) * K + k0 + tx] = __float2half_rn(t[tx][i]);
}

// ---------------- LayerNorm -> fp16 (mode1: shift+partition) ----------------
__global__ __launch_bounds__(128)
void ln_kernel(const float* __restrict__ x, const float* __restrict__ gamma,
               const float* __restrict__ beta, __half* __restrict__ oh, int mode)
{
    int tok = blockIdx.x;
    int src;
    if (mode == 1) {
        int w = tok / NWIN, n = tok - w * NWIN;
        int b = w >> 6, wi = w & 63;
        int wh = wi >> 3, ww = wi & 7;
        int i = n / WS, j = n - i * WS;
        int hp = wh * WS + i, wp = ww * WS + j;
        int hs = hp + SSH; if (hs >= HIMG) hs -= HIMG;
        int ws_ = wp + SSH; if (ws_ >= WIMG) ws_ -= WIMG;
        src = b * (HIMG * WIMG) + hs * WIMG + ws_;
    } else {
        src = tok;
    }
    int tid = threadIdx.x;
    int c = tid * 4;
    float4 v = *(const float4*)(x + (size_t)src * CH + c);
    float s  = v.x + v.y + v.z + v.w;
    float sq = v.x*v.x + v.y*v.y + v.z*v.z + v.w*v.w;
    #pragma unroll
    for (int off = 16; off; off >>= 1) {
        s  += __shfl_xor_sync(0xffffffffu, s, off);
        sq += __shfl_xor_sync(0xffffffffu, sq, off);
    }
    __shared__ float sh[8];
    int warp = tid >> 5, lane = tid & 31;
    if (lane == 0) { sh[warp] = s; sh[warp + 4] = sq; }
    __syncthreads();
    if (tid == 0) {
        float ts = sh[0] + sh[1] + sh[2] + sh[3];
        float tq = sh[4] + sh[5] + sh[6] + sh[7];
        float mean = ts * (1.0f / CH);
        float var = tq * (1.0f / CH) - mean * mean;
        sh[0] = mean; sh[1] = rsqrtf(var + 1e-5f);
    }
    __syncthreads();
    float mean = sh[0], inv = sh[1];
    float4 g4 = *(const float4*)(gamma + c);
    float4 b4 = *(const float4*)(beta + c);
    __half hh[4];
    hh[0] = __float2half_rn((v.x - mean) * inv * g4.x + b4.x);
    hh[1] = __float2half_rn((v.y - mean) * inv * g4.y + b4.y);
    hh[2] = __float2half_rn((v.z - mean) * inv * g4.z + b4.z);
    hh[3] = __float2half_rn((v.w - mean) * inv * g4.w + b4.w);
    *(uint2*)(oh + (size_t)tok * CH + c) = *(uint2*)hh;
}

// ---------------- fp16 GEMM via mma.sync ----------------
// Tile 128x128, 8 warps (4x2 grid, warp tile 32x64), K-chunk 64, 3 stages,
// 96KB smem -> 2 CTAs/SM.  EPI: 0 f32, 1 GELU->fp16, 2 f32 RMW, 3 fp16.
#define OFF_B   16384
#define STG_SZ  32768
#define TGEMM_SMEM (3 * STG_SZ)

template <int EPI>
__global__ void __launch_bounds__(256, 2)
tgemm(const __half* __restrict__ Ah, const __half* __restrict__ Bh,
      const float* __restrict__ bias, float* __restrict__ C,
      __half* __restrict__ Ch, int M, int N, int K)
{
    extern __shared__ __align__(128) char smem[];
    uint32_t sb = smem_u32(smem);
    int tid = threadIdx.x, wid = tid >> 5, lane = tid & 31;
    int m0 = blockIdx.y << 7, n0 = blockIdx.x << 7;
    int wm = wid & 3, wn = wid >> 2;

    // ---- loader coords: 128 rows x 128B, 2 threads/row, 4x16B each ----
    int ar = tid >> 1, ac = (tid & 1) * 4;
    const char* gA = (const char*)(Ah + (size_t)(m0 + ar) * K) + ac * 16;
    const char* gB = (const char*)(Bh + (size_t)(n0 + ar) * K) + ac * 16;
    uint32_t sw[4];
    #pragma unroll
    for (int j = 0; j < 4; ++j)
        sw[j] = (uint32_t)(ar * 128 + (((ac + j) ^ (ar & 7)) << 4));

    // ---- ldmatrix coords ----
    int arow = wm * 32 + (lane & 15);
    uint32_t aterm = (uint32_t)(arow * 128);
    int axor = arow & 7;
    int ac16 = lane >> 4;
    int brow = wn * 64 + ((lane >> 4) & 1) * 8 + (lane & 7);
    uint32_t bterm = (uint32_t)(brow * 128);
    int bxor = brow & 7;
    int bc16 = (lane >> 3) & 1;

    float acc[2][8][4];
    #pragma unroll
    for (int i = 0; i < 2; ++i)
        #pragma unroll
        for (int j = 0; j < 8; ++j)
            #pragma unroll
            for (int q = 0; q < 4; ++q) acc[i][j][q] = 0.0f;

    const int nch = K >> 6;

    // prologue: issue chunks 0,1
    #pragma unroll
    for (int pc = 0; pc < 2; ++pc) {
        uint32_t s = sb + pc * STG_SZ;
        size_t go = (size_t)pc * 128;
        #pragma unroll
        for (int j = 0; j < 4; ++j) {
            CP16(s + sw[j],         gA + go + j * 16);
            CP16(s + OFF_B + sw[j], gB + go + j * 16);
        }
        CPCOMMIT();
    }

    int buf = 0;
    for (int c = 0; c < nch; ++c) {
        if (c + 1 < nch) { CPWAIT1(); } else { CPWAIT0(); }
        __syncthreads();
        if (c + 2 < nch) {
            int b2 = buf + 2; if (b2 >= 3) b2 -= 3;
            uint32_t s = sb + b2 * STG_SZ;
            size_t go = (size_t)(c + 2) * 128;
            #pragma unroll
            for (int j = 0; j < 4; ++j) {
                CP16(s + sw[j],         gA + go + j * 16);
                CP16(s + OFF_B + sw[j], gB + go + j * 16);
            }
            CPCOMMIT();
        } else {
            CPCOMMIT();
        }

        uint32_t sS = sb + buf * STG_SZ;
        #pragma unroll
        for (int k16 = 0; k16 < 4; ++k16) {
            uint32_t ah[2][4];
            uint32_t aoff = aterm + ((uint32_t)((2 * k16 + ac16) ^ axor) << 4);
            LDSM4(ah[0], sS + aoff);
            LDSM4(ah[1], sS + aoff + 2048);
            uint32_t boff = bterm + ((uint32_t)((2 * k16 + bc16) ^ bxor) << 4);
            #pragma unroll
            for (int ng = 0; ng < 4; ++ng) {
                uint32_t bh[4];
                LDSM4(bh, sS + OFF_B + boff + ng * 2048);
                #pragma unroll
                for (int mt = 0; mt < 2; ++mt) {
                    mma_f16(acc[mt][2 * ng],     ah[mt], &bh[0]);
                    mma_f16(acc[mt][2 * ng + 1], ah[mt], &bh[2]);
                }
            }
        }
        if (++buf == 3) buf = 0;
    }

    // ---- epilogue ----
    int r0 = m0 + wm * 32 + (lane >> 2);
    int cb = n0 + wn * 64 + (lane & 3) * 2;
    #pragma unroll
    for (int mt = 0; mt < 2; ++mt) {
        #pragma unroll
        for (int n8 = 0; n8 < 8; ++n8) {
            int col = cb + n8 * 8;
            float2 bv = *(const float2*)(bias + col);
            #pragma unroll
            for (int rt = 0; rt < 2; ++rt) {
                int row = r0 + mt * 16 + rt * 8;
                float vx = acc[mt][n8][rt * 2]     + bv.x;
                float vy = acc[mt][n8][rt * 2 + 1] + bv.y;
                if (EPI == 0) {
                    float2 r = {vx, vy};
                    *(float2*)(C + (size_t)row * N + col) = r;
                } else if (EPI == 1) {
                    float gx = 0.5f * vx * (1.0f + erff(vx * 0.70710678118654752f));
                    float gy = 0.5f * vy * (1.0f + erff(vy * 0.70710678118654752f));
                    __half hh[2];
                    hh[0] = __float2half_rn(gx);
                    hh[1] = __float2half_rn(gy);
                    *(uint32_t*)(Ch + (size_t)row * N + col) = *(uint32_t*)hh;
                } else if (EPI == 2) {
                    float* cp = C + (size_t)row * N + col;
                    float2 old = *(const float2*)cp;
                    float2 r = {vx + old.x, vy + old.y};
                    *(float2*)cp = r;
                } else {
                    __half hh[2];
                    hh[0] = __float2half_rn(vx);
                    hh[1] = __float2half_rn(vy);
                    *(uint32_t*)(Ch + (size_t)row * N + col) = *(uint32_t*)hh;
                }
            }
        }
    }
}

// ---------------- windowed attention (fp16 in, fp16 out) ----------------
__global__ __launch_bounds__(256)
void attn_kernel(const __half* __restrict__ qkv, const float* __restrict__ table,
                 const int* __restrict__ relidx, const float* __restrict__ mask,
                 __half* __restrict__ oh)
{
    __shared__ float sq[NWIN * 36];
    __shared__ float sk[NWIN * 36];
    __shared__ float sv[NWIN * 36];
    __shared__ float ss[NWIN * 52];

    int bh = blockIdx.x;
    int b = bh >> 4, h = bh & 15;
    int tid = threadIdx.x;

    for (int idx = tid; idx < NWIN * 16; idx += 256) {
        int n = idx >> 4, d = (idx & 15) * 2;
        size_t base = (size_t)(b * NWIN + n) * (3 * CH) + h * HD + d;
        float2 q2 = __half22float2(*(const __half2*)(qkv + base));
        float2 k2 = __half22float2(*(const __half2*)(qkv + base + CH));
        float2 v2 = __half22float2(*(const __half2*)(qkv + base + 2 * CH));
        sq[n * 36 + d] = q2.x * SCALE; sq[n * 36 + d + 1] = q2.y * SCALE;
        sk[n * 36 + d] = k2.x;         sk[n * 36 + d + 1] = k2.y;
        sv[n * 36 + d] = v2.x;         sv[n * 36 + d + 1] = v2.y;
    }
    __syncthreads();

    int wi = b & 63;
    for (int idx = tid; idx < NWIN * NWIN; idx += 256) {
        int n = idx / NWIN, m = idx - n * NWIN;
        const float4* qp = (const float4*)&sq[n * 36];
        const float4* kp = (const float4*)&sk[m * 36];
        float acc = 0.0f;
        #pragma unroll
        for (int t = 0; t < 8; ++t) {
            float4 a = qp[t], c4 = kp[t];
            acc += a.x * c4.x + a.y * c4.y + a.z * c4.z + a.w * c4.w;
        }
        acc += table[relidx[idx] * NHEAD + h];
        acc += mask[(size_t)wi * (NWIN * NWIN) + idx];
        ss[n * 52 + m] = acc;
    }
    __syncthreads();

    int warp = tid >> 5, lane = tid & 31;
    for (int r = warp; r < NWIN; r += 8) {
        float v1 = ss[r * 52 + lane];
        float v2 = (lane + 32 < NWIN) ? ss[r * 52 + lane + 32] : -1e30f;
        float mx = fmaxf(v1, v2);
        #pragma unroll
        for (int off = 16; off; off >>= 1)
            mx = fmaxf(mx, __shfl_xor_sync(0xffffffffu, mx, off));
        float e1 = expf(v1 - mx);
        float e2 = (lane + 32 < NWIN) ? expf(v2 - mx) : 0.0f;
        float sum = e1 + e2;
        #pragma unroll
        for (int off = 16; off; off >>= 1)
            sum += __shfl_xor_sync(0xffffffffu, sum, off);
        float inv = 1.0f / sum;
        ss[r * 52 + lane] = e1 * inv;
        if (lane + 32 < NWIN) ss[r * 52 + lane + 32] = e2 * inv;
    }
    __syncthreads();

    // P @ V, float2-vectorized over d
    for (int idx = tid; idx < NWIN * 16; idx += 256) {
        int n = idx >> 4, d = (idx & 15) * 2;
        const float* pp = &ss[n * 52];
        float ax = 0.0f, ay = 0.0f;
        #pragma unroll
        for (int m = 0; m < NWIN; ++m) {
            float p = pp[m];
            float2 v2 = *(const float2*)&sv[m * 36 + d];
            ax += p * v2.x; ay += p * v2.y;
        }
        __half2 r = __floats2half2_rn(ax, ay);
        *(__half2*)(oh + (size_t)(b * NWIN + n) * CH + h * HD + d) = r;
    }
}

// ---------------- fused: reverse+roll+residual -> out, then LN2 -> yh ----------------
__global__ __launch_bounds__(128)
void fuse2_kernel(const float* __restrict__ x, const float* __restrict__ proj,
                  const float* __restrict__ gamma, const float* __restrict__ beta,
                  float* __restrict__ out, __half* __restrict__ yh)
{
    int tok = blockIdx.x;
    int b = tok / (HIMG * WIMG);
    int rem = tok - b * (HIMG * WIMG);
    int hp0 = rem / WIMG, wp0 = rem - hp0 * WIMG;
    int hp = hp0 - SSH; if (hp < 0) hp += HIMG;
    int wp = wp0 - SSH; if (wp < 0) wp += WIMG;
    int wh = hp / WS, i = hp - wh * WS;
    int ww = wp / WS, j = wp - ww * WS;
    int src = (b * NW_IMG + wh * 8 + ww) * NWIN + i * WS + j;

    int tid = threadIdx.x;
    int c = tid * 4;
    float4 a = *(const float4*)(x + (size_t)tok * CH + c);
    float4 p = *(const float4*)(proj + (size_t)src * CH + c);
    a.x += p.x; a.y += p.y; a.z += p.z; a.w += p.w;
    *(float4*)(out + (size_t)tok * CH + c) = a;

    float s  = a.x + a.y + a.z + a.w;
    float sq = a.x*a.x + a.y*a.y + a.z*a.z + a.w*a.w;
    #pragma unroll
    for (int off = 16; off; off >>= 1) {
        s  += __shfl_xor_sync(0xffffffffu, s, off);
        sq += __shfl_xor_sync(0xffffffffu, sq, off);
    }
    __shared__ float sh[8];
    int warp = tid >> 5, lane = tid & 31;
    if (lane == 0) { sh[warp] = s; sh[warp + 4] = sq; }
    __syncthreads();
    if (tid == 0) {
        float ts = sh[0] + sh[1] + sh[2] + sh[3];
        float tq = sh[4] + sh[5] + sh[6] + sh[7];
        float mean = ts * (1.0f / CH);
        float var = tq * (1.0f / CH) - mean * mean;
        sh[0] = mean; sh[1] = rsqrtf(var + 1e-5f);
    }
    __syncthreads();
    float mean = sh[0], inv = sh[1];
    float4 g4 = *(const float4*)(gamma + c);
    float4 b4 = *(const float4*)(beta + c);
    __half hh[4];
    hh[0] = __float2half_rn((a.x - mean) * inv * g4.x + b4.x);
    hh[1] = __float2half_rn((a.y - mean) * inv * g4.y + b4.y);
    hh[2] = __float2half_rn((a.z - mean) * inv * g4.z + b4.z);
    hh[3] = __float2half_rn((a.w - mean) * inv * g4.w + b4.w);
    *(uint2*)(yh + (size_t)tok * CH + c) = *(uint2*)hh;
}

// ---------------- launcher ----------------
extern "C" void kernel_launch(void* const* d_in, const int* in_sizes, int n_in,
                              void* d_out, int out_size)
{
    const float* x        = (const float*)d_in[0];
    const float* norm1_g  = (const float*)d_in[1];
    const float* norm1_b  = (const float*)d_in[2];
    const float* qkv_w    = (const float*)d_in[3];
    const float* qkv_b    = (const float*)d_in[4];
    const float* rel_tab  = (const float*)d_in[5];
    const float* proj_w   = (const float*)d_in[6];
    const float* proj_b   = (const float*)d_in[7];
    const float* norm2_g  = (const float*)d_in[8];
    const float* norm2_b  = (const float*)d_in[9];
    const float* fc1_w    = (const float*)d_in[10];
    const float* fc1_b    = (const float*)d_in[11];
    const float* fc2_w    = (const float*)d_in[12];
    const float* fc2_b    = (const float*)d_in[13];
    const int*   rel_idx  = (const int*)d_in[14];
    const float* attn_msk = (const float*)d_in[15];
    float* out = (float*)d_out;

    unsigned char *R1, *R2;
    cudaGetSymbolAddress((void**)&R1, g_R1);
    cudaGetSymbolAddress((void**)&R2, g_R2);
    __half *qkvT, *projT, *fc1T, *fc2T;
    cudaGetSymbolAddress((void**)&qkvT, g_qkvT);
    cudaGetSymbolAddress((void**)&projT, g_projT);
    cudaGetSymbolAddress((void**)&fc1T, g_fc1T);
    cudaGetSymbolAddress((void**)&fc2T, g_fc2T);

    __half* qkv = (__half*)R1;                                  // fp16 308MB
    float* proj = (float*)(R1 + (size_t)MTOK * 3 * CH * 2);     // fp32 205MB, disjoint
    __half* hid = (__half*)R1;                                  // reuses dead qkv region
    __half* act = (__half*)R2;                                  // wins -> o -> y

    cudaFuncSetAttribute(tgemm<0>, cudaFuncAttributeMaxDynamicSharedMemorySize, TGEMM_SMEM);
    cudaFuncSetAttribute(tgemm<1>, cudaFuncAttributeMaxDynamicSharedMemorySize, TGEMM_SMEM);
    cudaFuncSetAttribute(tgemm<2>, cudaFuncAttributeMaxDynamicSharedMemorySize, TGEMM_SMEM);
    cudaFuncSetAttribute(tgemm<3>, cudaFuncAttributeMaxDynamicSharedMemorySize, TGEMM_SMEM);

    // 0) weight transpose to fp16 [N,K]
    wsplit_kernel<<<dim3(3 * CH / 32, CH / 32), 256>>>(qkv_w,  qkvT, CH, 3 * CH);
    wsplit_kernel<<<dim3(CH / 32,     CH / 32), 256>>>(proj_w, projT, CH, CH);
    wsplit_kernel<<<dim3(HID / 32,    CH / 32), 256>>>(fc1_w,  fc1T, CH, HID);
    wsplit_kernel<<<dim3(CH / 32,    HID / 32), 256>>>(fc2_w,  fc2T, HID, CH);

    // 1) LN1 + shift + window partition
    ln_kernel<<<MTOK, 128>>>(x, norm1_g, norm1_b, act, 1);

    // 2) QKV GEMM (100352 x 1536 x 512) -> fp16
    tgemm<3><<<dim3(3 * CH / 128, MTOK / 128), 256, TGEMM_SMEM>>>(
        act, qkvT, qkv_b, nullptr, qkv, MTOK, 3 * CH, CH);

    // 3) attention
    attn_kernel<<<BN * NHEAD, 256>>>(qkv, rel_tab, rel_idx, attn_msk, act);

    // 4) proj GEMM (100352 x 512 x 512) -> fp32
    tgemm<0><<<dim3(CH / 128, MTOK / 128), 256, TGEMM_SMEM>>>(
        act, projT, proj_b, proj, nullptr, MTOK, CH, CH);

    // 5+6) reverse + residual -> d_out, fused LN2
    fuse2_kernel<<<MTOK, 128>>>(x, proj, norm2_g, norm2_b, out, act);

    // 7) FC1 + GELU (100352 x 2048 x 512) -> fp16 hid
    tgemm<1><<<dim3(HID / 128, MTOK / 128), 256, TGEMM_SMEM>>>(
        act, fc1T, fc1_b, nullptr, hid, MTOK, HID, CH);

    // 8) FC2 + residual into d_out (100352 x 512 x 2048)
    tgemm<2><<<dim3(CH / 128, MTOK / 128), 256, TGEMM_SMEM>>>(
        hid, fc2T, fc2_b, out, nullptr, MTOK, CH, HID);

    (void)in_sizes; (void)n_in; (void)out_size;
}

// round 9
// speedup vs baseline: 4.6500x; 1.2123x over previous
#include <cuda_runtime.h>
#include <cuda_fp16.h>
#include <math.h>
#include <stdint.h>

// ---------------- problem constants ----------------
#define BATCH   32
#define HIMG    56
#define WIMG    56
#define CH      512
#define NHEAD   16
#define WS      7
#define SSH     3
#define HD      32
#define NWIN    49
#define NW_IMG  64
#define BN      (BATCH*NW_IMG)      // 2048 windows
#define MTOK    (BN*NWIN)           // 100352 tokens
#define HID     2048
#define SCALE   0.17677669529663687f
#define NN      (NWIN*NWIN)         // 2401

// ---------------- scratch ----------------
__device__ __align__(128) unsigned char g_R1[(size_t)MTOK * HID * 4];
__device__ __align__(128) unsigned char g_R2[(size_t)MTOK * CH * 2];

__device__ __align__(128) __half g_qkvT[3 * CH * CH];
__device__ __align__(128) __half g_projT[CH * CH];
__device__ __align__(128) __half g_fc1T[HID * CH];
__device__ __align__(128) __half g_fc2T[CH * HID];

// ---------------- helpers ----------------
__device__ __forceinline__ uint32_t smem_u32(const void* p) {
    uint32_t a;
    asm("{ .reg .u64 t; cvta.to.shared.u64 t, %1; cvt.u32.u64 %0, t; }" : "=r"(a) : "l"(p));
    return a;
}
#define CP16(dst, src) \
    asm volatile("cp.async.cg.shared.global [%0], [%1], 16;" :: "r"(dst), "l"(src))
#define CPCOMMIT() asm volatile("cp.async.commit_group;" ::: "memory")
#define CPWAIT1()  asm volatile("cp.async.wait_group 1;" ::: "memory")
#define CPWAIT0()  asm volatile("cp.async.wait_group 0;" ::: "memory")

#define LDSM4(r, a) \
    asm volatile("ldmatrix.sync.aligned.m8n8.x4.shared.b16 {%0,%1,%2,%3}, [%4];" \
        : "=r"((r)[0]), "=r"((r)[1]), "=r"((r)[2]), "=r"((r)[3]) : "r"(a))

__device__ __forceinline__ void mma_f16(float* c, const uint32_t* a, const uint32_t* b) {
    asm volatile("mma.sync.aligned.m16n8k16.row.col.f32.f16.f16.f32 "
        "{%0,%1,%2,%3}, {%4,%5,%6,%7}, {%8,%9}, {%0,%1,%2,%3};"
        : "+f"(c[0]), "+f"(c[1]), "+f"(c[2]), "+f"(c[3])
        : "r"(a[0]), "r"(a[1]), "r"(a[2]), "r"(a[3]), "r"(b[0]), "r"(b[1]));
}

// ---------------- weight transpose: W[K,N] -> Wt[N,K] fp16 ----------------
__global__ __launch_bounds__(256)
void wsplit_kernel(const float* __restrict__ W, __half* __restrict__ oh, int K, int N)
{
    __shared__ float t[32][33];
    int n0 = blockIdx.x * 32, k0 = blockIdx.y * 32;
    int tx = threadIdx.x & 31, ty = threadIdx.x >> 5;
    #pragma unroll
    for (int i = ty; i < 32; i += 8)
        t[i][tx] = W[(size_t)(k0 + i) * N + n0 + tx];
    __syncthreads();
    #pragma unroll
    for (int i = ty; i < 32; i += 8)
        oh[(size_t)(n0 + i) * K + k0 + tx] = __float2half_rn(t[tx][i]);
}

// ---------------- fused rel-pos bias + window mask table ----------------
// fusedb[(wi*16+h)*NN + idx] = table[relidx[idx]*NHEAD+h] + mask[wi*NN+idx]
__global__ __launch_bounds__(256)
void fusedbias_kernel(const float* __restrict__ table, const int* __restrict__ relidx,
                      const float* __restrict__ mask, float* __restrict__ fusedb)
{
    int wi = blockIdx.x >> 4, h = blockIdx.x & 15;
    float* dst = fusedb + (size_t)blockIdx.x * NN;
    const float* mrow = mask + (size_t)wi * NN;
    for (int i = threadIdx.x; i < NN; i += 256)
        dst[i] = table[relidx[i] * NHEAD + h] + mrow[i];
}

// ---------------- LayerNorm -> fp16 (mode1: shift+partition) ----------------
__global__ __launch_bounds__(128)
void ln_kernel(const float* __restrict__ x, const float* __restrict__ gamma,
               const float* __restrict__ beta, __half* __restrict__ oh, int mode)
{
    int tok = blockIdx.x;
    int src;
    if (mode == 1) {
        int w = tok / NWIN, n = tok - w * NWIN;
        int b = w >> 6, wi = w & 63;
        int wh = wi >> 3, ww = wi & 7;
        int i = n / WS, j = n - i * WS;
        int hp = wh * WS + i, wp = ww * WS + j;
        int hs = hp + SSH; if (hs >= HIMG) hs -= HIMG;
        int ws_ = wp + SSH; if (ws_ >= WIMG) ws_ -= WIMG;
        src = b * (HIMG * WIMG) + hs * WIMG + ws_;
    } else {
        src = tok;
    }
    int tid = threadIdx.x;
    int c = tid * 4;
    float4 v = *(const float4*)(x + (size_t)src * CH + c);
    float s  = v.x + v.y + v.z + v.w;
    float sq = v.x*v.x + v.y*v.y + v.z*v.z + v.w*v.w;
    #pragma unroll
    for (int off = 16; off; off >>= 1) {
        s  += __shfl_xor_sync(0xffffffffu, s, off);
        sq += __shfl_xor_sync(0xffffffffu, sq, off);
    }
    __shared__ float sh[8];
    int warp = tid >> 5, lane = tid & 31;
    if (lane == 0) { sh[warp] = s; sh[warp + 4] = sq; }
    __syncthreads();
    if (tid == 0) {
        float ts = sh[0] + sh[1] + sh[2] + sh[3];
        float tq = sh[4] + sh[5] + sh[6] + sh[7];
        float mean = ts * (1.0f / CH);
        float var = tq * (1.0f / CH) - mean * mean;
        sh[0] = mean; sh[1] = rsqrtf(var + 1e-5f);
    }
    __syncthreads();
    float mean = sh[0], inv = sh[1];
    float4 g4 = *(const float4*)(gamma + c);
    float4 b4 = *(const float4*)(beta + c);
    __half hh[4];
    hh[0] = __float2half_rn((v.x - mean) * inv * g4.x + b4.x);
    hh[1] = __float2half_rn((v.y - mean) * inv * g4.y + b4.y);
    hh[2] = __float2half_rn((v.z - mean) * inv * g4.z + b4.z);
    hh[3] = __float2half_rn((v.w - mean) * inv * g4.w + b4.w);
    *(uint2*)(oh + (size_t)tok * CH + c) = *(uint2*)hh;
}

// ---------------- fp16 GEMM via mma.sync (unchanged from R8) ----------------
#define OFF_B   16384
#define STG_SZ  32768
#define TGEMM_SMEM (3 * STG_SZ)

template <int EPI>
__global__ void __launch_bounds__(256, 2)
tgemm(const __half* __restrict__ Ah, const __half* __restrict__ Bh,
      const float* __restrict__ bias, float* __restrict__ C,
      __half* __restrict__ Ch, int M, int N, int K)
{
    extern __shared__ __align__(128) char smem[];
    uint32_t sb = smem_u32(smem);
    int tid = threadIdx.x, wid = tid >> 5, lane = tid & 31;
    int m0 = blockIdx.y << 7, n0 = blockIdx.x << 7;
    int wm = wid & 3, wn = wid >> 2;

    int ar = tid >> 1, ac = (tid & 1) * 4;
    const char* gA = (const char*)(Ah + (size_t)(m0 + ar) * K) + ac * 16;
    const char* gB = (const char*)(Bh + (size_t)(n0 + ar) * K) + ac * 16;
    uint32_t sw[4];
    #pragma unroll
    for (int j = 0; j < 4; ++j)
        sw[j] = (uint32_t)(ar * 128 + (((ac + j) ^ (ar & 7)) << 4));

    int arow = wm * 32 + (lane & 15);
    uint32_t aterm = (uint32_t)(arow * 128);
    int axor = arow & 7;
    int ac16 = lane >> 4;
    int brow = wn * 64 + ((lane >> 4) & 1) * 8 + (lane & 7);
    uint32_t bterm = (uint32_t)(brow * 128);
    int bxor = brow & 7;
    int bc16 = (lane >> 3) & 1;

    float acc[2][8][4];
    #pragma unroll
    for (int i = 0; i < 2; ++i)
        #pragma unroll
        for (int j = 0; j < 8; ++j)
            #pragma unroll
            for (int q = 0; q < 4; ++q) acc[i][j][q] = 0.0f;

    const int nch = K >> 6;

    #pragma unroll
    for (int pc = 0; pc < 2; ++pc) {
        uint32_t s = sb + pc * STG_SZ;
        size_t go = (size_t)pc * 128;
        #pragma unroll
        for (int j = 0; j < 4; ++j) {
            CP16(s + sw[j],         gA + go + j * 16);
            CP16(s + OFF_B + sw[j], gB + go + j * 16);
        }
        CPCOMMIT();
    }

    int buf = 0;
    for (int c = 0; c < nch; ++c) {
        if (c + 1 < nch) { CPWAIT1(); } else { CPWAIT0(); }
        __syncthreads();
        if (c + 2 < nch) {
            int b2 = buf + 2; if (b2 >= 3) b2 -= 3;
            uint32_t s = sb + b2 * STG_SZ;
            size_t go = (size_t)(c + 2) * 128;
            #pragma unroll
            for (int j = 0; j < 4; ++j) {
                CP16(s + sw[j],         gA + go + j * 16);
                CP16(s + OFF_B + sw[j], gB + go + j * 16);
            }
            CPCOMMIT();
        } else {
            CPCOMMIT();
        }

        uint32_t sS = sb + buf * STG_SZ;
        #pragma unroll
        for (int k16 = 0; k16 < 4; ++k16) {
            uint32_t ah[2][4];
            uint32_t aoff = aterm + ((uint32_t)((2 * k16 + ac16) ^ axor) << 4);
            LDSM4(ah[0], sS + aoff);
            LDSM4(ah[1], sS + aoff + 2048);
            uint32_t boff = bterm + ((uint32_t)((2 * k16 + bc16) ^ bxor) << 4);
            #pragma unroll
            for (int ng = 0; ng < 4; ++ng) {
                uint32_t bh[4];
                LDSM4(bh, sS + OFF_B + boff + ng * 2048);
                #pragma unroll
                for (int mt = 0; mt < 2; ++mt) {
                    mma_f16(acc[mt][2 * ng],     ah[mt], &bh[0]);
                    mma_f16(acc[mt][2 * ng + 1], ah[mt], &bh[2]);
                }
            }
        }
        if (++buf == 3) buf = 0;
    }

    int r0 = m0 + wm * 32 + (lane >> 2);
    int cb = n0 + wn * 64 + (lane & 3) * 2;
    #pragma unroll
    for (int mt = 0; mt < 2; ++mt) {
        #pragma unroll
        for (int n8 = 0; n8 < 8; ++n8) {
            int col = cb + n8 * 8;
            float2 bv = *(const float2*)(bias + col);
            #pragma unroll
            for (int rt = 0; rt < 2; ++rt) {
                int row = r0 + mt * 16 + rt * 8;
                float vx = acc[mt][n8][rt * 2]     + bv.x;
                float vy = acc[mt][n8][rt * 2 + 1] + bv.y;
                if (EPI == 0) {
                    float2 r = {vx, vy};
                    *(float2*)(C + (size_t)row * N + col) = r;
                } else if (EPI == 1) {
                    float gx = 0.5f * vx * (1.0f + erff(vx * 0.70710678118654752f));
                    float gy = 0.5f * vy * (1.0f + erff(vy * 0.70710678118654752f));
                    __half hh[2];
                    hh[0] = __float2half_rn(gx);
                    hh[1] = __float2half_rn(gy);
                    *(uint32_t*)(Ch + (size_t)row * N + col) = *(uint32_t*)hh;
                } else if (EPI == 2) {
                    float* cp = C + (size_t)row * N + col;
                    float2 old = *(const float2*)cp;
                    float2 r = {vx + old.x, vy + old.y};
                    *(float2*)cp = r;
                } else {
                    __half hh[2];
                    hh[0] = __float2half_rn(vx);
                    hh[1] = __float2half_rn(vy);
                    *(uint32_t*)(Ch + (size_t)row * N + col) = *(uint32_t*)hh;
                }
            }
        }
    }
}

// ---------------- windowed attention v2 (fp16 smem, 2x2 blocking) ----------------
#define QR 40   // half-stride per row (80B, 16B-aligned)
__global__ __launch_bounds__(256)
void attn_kernel(const __half* __restrict__ qkv, const float* __restrict__ fusedb,
                 __half* __restrict__ oh)
{
    __shared__ __half sq[50 * QR], sk[50 * QR], sv[50 * QR];
    __shared__ float ss[50 * 52];

    int bh = blockIdx.x;
    int b = bh >> 4, h = bh & 15;
    int tid = threadIdx.x;
    const float* fb = fusedb + (size_t)(((b & 63) << 4) + h) * NN;

    // load q/k/v rows (49 x 32 halves, 4 x uint4 per row)
    for (int idx = tid; idx < NWIN * 4; idx += 256) {
        int n = idx >> 2, d8 = (idx & 3) << 3;
        size_t base = (size_t)(b * NWIN + n) * (3 * CH) + h * HD + d8;
        *(uint4*)&sq[n * QR + d8] = *(const uint4*)(qkv + base);
        *(uint4*)&sk[n * QR + d8] = *(const uint4*)(qkv + base + CH);
        *(uint4*)&sv[n * QR + d8] = *(const uint4*)(qkv + base + 2 * CH);
    }
    __syncthreads();

    // scores, 2x2 register blocking over (n, m)
    for (int idx = tid; idx < 625; idx += 256) {
        int np = idx / 25, mp = idx - np * 25;
        int n0 = np * 2, m0 = mp * 2;
        int n1 = n0 + 1, m1 = m0 + 1;
        float a00 = 0.f, a01 = 0.f, a10 = 0.f, a11 = 0.f;
        #pragma unroll
        for (int t = 0; t < 4; ++t) {
            union { uint4 u; __half2 hx[4]; } q0, q1, k0, k1;
            q0.u = *(const uint4*)&sq[n0 * QR + t * 8];
            q1.u = *(const uint4*)&sq[n1 * QR + t * 8];
            k0.u = *(const uint4*)&sk[m0 * QR + t * 8];
            k1.u = *(const uint4*)&sk[m1 * QR + t * 8];
            #pragma unroll
            for (int j = 0; j < 4; ++j) {
                float2 fq0 = __half22float2(q0.hx[j]);
                float2 fq1 = __half22float2(q1.hx[j]);
                float2 fk0 = __half22float2(k0.hx[j]);
                float2 fk1 = __half22float2(k1.hx[j]);
                a00 += fq0.x * fk0.x + fq0.y * fk0.y;
                a01 += fq0.x * fk1.x + fq0.y * fk1.y;
                a10 += fq1.x * fk0.x + fq1.y * fk0.y;
                a11 += fq1.x * fk1.x + fq1.y * fk1.y;
            }
        }
        bool nv = (n1 < NWIN), mv = (m1 < NWIN);
        ss[n0 * 52 + m0] = a00 * SCALE + fb[n0 * NWIN + m0];
        if (mv) ss[n0 * 52 + m1] = a01 * SCALE + fb[n0 * NWIN + m1];
        if (nv) {
            ss[n1 * 52 + m0] = a10 * SCALE + fb[n1 * NWIN + m0];
            if (mv) ss[n1 * 52 + m1] = a11 * SCALE + fb[n1 * NWIN + m1];
        }
    }
    __syncthreads();

    int warp = tid >> 5, lane = tid & 31;
    for (int r = warp; r < NWIN; r += 8) {
        float v1 = ss[r * 52 + lane];
        float v2 = (lane + 32 < NWIN) ? ss[r * 52 + lane + 32] : -1e30f;
        float mx = fmaxf(v1, v2);
        #pragma unroll
        for (int off = 16; off; off >>= 1)
            mx = fmaxf(mx, __shfl_xor_sync(0xffffffffu, mx, off));
        float e1 = expf(v1 - mx);
        float e2 = (lane + 32 < NWIN) ? expf(v2 - mx) : 0.0f;
        float sum = e1 + e2;
        #pragma unroll
        for (int off = 16; off; off >>= 1)
            sum += __shfl_xor_sync(0xffffffffu, sum, off);
        float inv = 1.0f / sum;
        ss[r * 52 + lane] = e1 * inv;
        if (lane + 32 < NWIN) ss[r * 52 + lane + 32] = e2 * inv;
    }
    __syncthreads();

    // P @ V: 25 n-pairs x 16 d-pairs
    for (int idx = tid; idx < 400; idx += 256) {
        int np = idx >> 4, dp = idx & 15;
        int n0 = np * 2, n1 = n0 + 1, d = dp * 2;
        const float* p0 = &ss[n0 * 52];
        const float* p1 = &ss[n1 * 52];
        float ax0 = 0.f, ay0 = 0.f, ax1 = 0.f, ay1 = 0.f;
        #pragma unroll 7
        for (int m = 0; m < NWIN; ++m) {
            float2 vf = __half22float2(*(const __half2*)&sv[m * QR + d]);
            float b0 = p0[m], b1 = p1[m];
            ax0 += b0 * vf.x; ay0 += b0 * vf.y;
            ax1 += b1 * vf.x; ay1 += b1 * vf.y;
        }
        size_t ob = (size_t)(b * NWIN + n0) * CH + h * HD + d;
        *(__half2*)(oh + ob) = __floats2half2_rn(ax0, ay0);
        if (n1 < NWIN)
            *(__half2*)(oh + ob + CH) = __floats2half2_rn(ax1, ay1);
    }
}

// ---------------- fused: reverse+roll+residual -> out, then LN2 -> yh ----------------
__global__ __launch_bounds__(128)
void fuse2_kernel(const float* __restrict__ x, const float* __restrict__ proj,
                  const float* __restrict__ gamma, const float* __restrict__ beta,
                  float* __restrict__ out, __half* __restrict__ yh)
{
    int tok = blockIdx.x;
    int b = tok / (HIMG * WIMG);
    int rem = tok - b * (HIMG * WIMG);
    int hp0 = rem / WIMG, wp0 = rem - hp0 * WIMG;
    int hp = hp0 - SSH; if (hp < 0) hp += HIMG;
    int wp = wp0 - SSH; if (wp < 0) wp += WIMG;
    int wh = hp / WS, i = hp - wh * WS;
    int ww = wp / WS, j = wp - ww * WS;
    int src = (b * NW_IMG + wh * 8 + ww) * NWIN + i * WS + j;

    int tid = threadIdx.x;
    int c = tid * 4;
    float4 a = *(const float4*)(x + (size_t)tok * CH + c);
    float4 p = *(const float4*)(proj + (size_t)src * CH + c);
    a.x += p.x; a.y += p.y; a.z += p.z; a.w += p.w;
    *(float4*)(out + (size_t)tok * CH + c) = a;

    float s  = a.x + a.y + a.z + a.w;
    float sq = a.x*a.x + a.y*a.y + a.z*a.z + a.w*a.w;
    #pragma unroll
    for (int off = 16; off; off >>= 1) {
        s  += __shfl_xor_sync(0xffffffffu, s, off);
        sq += __shfl_xor_sync(0xffffffffu, sq, off);
    }
    __shared__ float sh[8];
    int warp = tid >> 5, lane = tid & 31;
    if (lane == 0) { sh[warp] = s; sh[warp + 4] = sq; }
    __syncthreads();
    if (tid == 0) {
        float ts = sh[0] + sh[1] + sh[2] + sh[3];
        float tq = sh[4] + sh[5] + sh[6] + sh[7];
        float mean = ts * (1.0f / CH);
        float var = tq * (1.0f / CH) - mean * mean;
        sh[0] = mean; sh[1] = rsqrtf(var + 1e-5f);
    }
    __syncthreads();
    float mean = sh[0], inv = sh[1];
    float4 g4 = *(const float4*)(gamma + c);
    float4 b4 = *(const float4*)(beta + c);
    __half hh[4];
    hh[0] = __float2half_rn((a.x - mean) * inv * g4.x + b4.x);
    hh[1] = __float2half_rn((a.y - mean) * inv * g4.y + b4.y);
    hh[2] = __float2half_rn((a.z - mean) * inv * g4.z + b4.z);
    hh[3] = __float2half_rn((a.w - mean) * inv * g4.w + b4.w);
    *(uint2*)(yh + (size_t)tok * CH + c) = *(uint2*)hh;
}

// ---------------- launcher ----------------
extern "C" void kernel_launch(void* const* d_in, const int* in_sizes, int n_in,
                              void* d_out, int out_size)
{
    const float* x        = (const float*)d_in[0];
    const float* norm1_g  = (const float*)d_in[1];
    const float* norm1_b  = (const float*)d_in[2];
    const float* qkv_w    = (const float*)d_in[3];
    const float* qkv_b    = (const float*)d_in[4];
    const float* rel_tab  = (const float*)d_in[5];
    const float* proj_w   = (const float*)d_in[6];
    const float* proj_b   = (const float*)d_in[7];
    const float* norm2_g  = (const float*)d_in[8];
    const float* norm2_b  = (const float*)d_in[9];
    const float* fc1_w    = (const float*)d_in[10];
    const float* fc1_b    = (const float*)d_in[11];
    const float* fc2_w    = (const float*)d_in[12];
    const float* fc2_b    = (const float*)d_in[13];
    const int*   rel_idx  = (const int*)d_in[14];
    const float* attn_msk = (const float*)d_in[15];
    float* out = (float*)d_out;

    unsigned char *R1, *R2;
    cudaGetSymbolAddress((void**)&R1, g_R1);
    cudaGetSymbolAddress((void**)&R2, g_R2);
    __half *qkvT, *projT, *fc1T, *fc2T;
    cudaGetSymbolAddress((void**)&qkvT, g_qkvT);
    cudaGetSymbolAddress((void**)&projT, g_projT);
    cudaGetSymbolAddress((void**)&fc1T, g_fc1T);
    cudaGetSymbolAddress((void**)&fc2T, g_fc2T);

    __half* qkv = (__half*)R1;                                  // fp16 308MB
    float* proj = (float*)(R1 + (size_t)MTOK * 3 * CH * 2);     // fp32 205MB
    float* fusedb = (float*)(R1 + (size_t)600 * 1024 * 1024);   // 9.8MB
    __half* hid = (__half*)R1;                                  // reuses dead qkv region
    __half* act = (__half*)R2;                                  // wins -> o -> y

    cudaFuncSetAttribute(tgemm<0>, cudaFuncAttributeMaxDynamicSharedMemorySize, TGEMM_SMEM);
    cudaFuncSetAttribute(tgemm<1>, cudaFuncAttributeMaxDynamicSharedMemorySize, TGEMM_SMEM);
    cudaFuncSetAttribute(tgemm<2>, cudaFuncAttributeMaxDynamicSharedMemorySize, TGEMM_SMEM);
    cudaFuncSetAttribute(tgemm<3>, cudaFuncAttributeMaxDynamicSharedMemorySize, TGEMM_SMEM);

    // 0) weight transpose + fused bias table
    wsplit_kernel<<<dim3(3 * CH / 32, CH / 32), 256>>>(qkv_w,  qkvT, CH, 3 * CH);
    wsplit_kernel<<<dim3(CH / 32,     CH / 32), 256>>>(proj_w, projT, CH, CH);
    wsplit_kernel<<<dim3(HID / 32,    CH / 32), 256>>>(fc1_w,  fc1T, CH, HID);
    wsplit_kernel<<<dim3(CH / 32,    HID / 32), 256>>>(fc2_w,  fc2T, HID, CH);
    fusedbias_kernel<<<NW_IMG * NHEAD, 256>>>(rel_tab, rel_idx, attn_msk, fusedb);

    // 1) LN1 + shift + window partition
    ln_kernel<<<MTOK, 128>>>(x, norm1_g, norm1_b, act, 1);

    // 2) QKV GEMM -> fp16
    tgemm<3><<<dim3(3 * CH / 128, MTOK / 128), 256, TGEMM_SMEM>>>(
        act, qkvT, qkv_b, nullptr, qkv, MTOK, 3 * CH, CH);

    // 3) attention
    attn_kernel<<<BN * NHEAD, 256>>>(qkv, fusedb, act);

    // 4) proj GEMM -> fp32
    tgemm<0><<<dim3(CH / 128, MTOK / 128), 256, TGEMM_SMEM>>>(
        act, projT, proj_b, proj, nullptr, MTOK, CH, CH);

    // 5+6) reverse + residual -> d_out, fused LN2
    fuse2_kernel<<<MTOK, 128>>>(x, proj, norm2_g, norm2_b, out, act);

    // 7) FC1 + GELU -> fp16 hid
    tgemm<1><<<dim3(HID / 128, MTOK / 128), 256, TGEMM_SMEM>>>(
        act, fc1T, fc1_b, nullptr, hid, MTOK, HID, CH);

    // 8) FC2 + residual into d_out
    tgemm<2><<<dim3(CH / 128, MTOK / 128), 256, TGEMM_SMEM>>>(
        hid, fc2T, fc2_b, out, nullptr, MTOK, CH, HID);

    (void)in_sizes; (void)n_in; (void)out_size;
}